// round 1
// baseline (speedup 1.0000x reference)
#include <cuda_runtime.h>
#include <math.h>

// Model dims
constexpr int B = 32, T = 40, P = 256, V = 4096, D = 256, DINO = 384, H = 4, L = 2;
constexpr int HD = 64, DFF = 1024;
constexpr float EPS = 1e-5f;

// ---------------- scratch (device globals; no allocation) ----------------
__device__ float g_x[B * T * D];
__device__ float g_y[B * T * D];
__device__ float g_qkv[B * T * 3 * D];
__device__ float g_ctx[B * T * D];
__device__ float g_h[B * T * DFF];
__device__ float g_ctxs[B * T * D];
__device__ float g_pproj[B * P * D];
__device__ float g_cproj[B * T * D];
__device__ float g_u[B * T * D];
__device__ float g_c0[B * T];

// ---------------- embed: x = tok_emb[tokens] + pos_emb ----------------
__global__ void embed_kernel(const int* __restrict__ tokens,
                             const float* __restrict__ tok_emb,
                             const float* __restrict__ pos_emb,
                             float* __restrict__ x) {
    int bt = blockIdx.x;
    int d = threadIdx.x;
    int t = bt % T;
    int tok = tokens[bt];
    x[(size_t)bt * D + d] = tok_emb[(size_t)tok * D + d] + pos_emb[(size_t)t * D + d];
}

// ---------------- generic SGEMM: C[m,n] = sum_k A[m,k]*W[n*ldw+k] (+bias)(+res)(relu) --
// Requires: M%64==0, N%64==0, K%16==0. 256 threads, 64x64x16 tiles, 4x4 micro-tile.
template <bool RELU>
__global__ void __launch_bounds__(256) sgemm_kernel(
    const float* __restrict__ A, const float* __restrict__ W,
    const float* __restrict__ bias, const float* __restrict__ res,
    float* __restrict__ C, int M, int N, int K, int ldw) {
    constexpr int BM = 64, BN = 64, BK = 16;
    __shared__ float As[BK][BM];
    __shared__ float Ws[BK][BN];
    int tid = threadIdx.x;
    int m0 = blockIdx.y * BM;
    int n0 = blockIdx.x * BN;
    int tx = tid & 15;   // n micro index
    int ty = tid >> 4;   // m micro index
    int lrow = tid >> 2;          // 0..63
    int lk4 = (tid & 3) * 4;      // 0,4,8,12
    float acc[4][4] = {};
    for (int k0 = 0; k0 < K; k0 += BK) {
        float4 a4 = *reinterpret_cast<const float4*>(&A[(size_t)(m0 + lrow) * K + k0 + lk4]);
        As[lk4 + 0][lrow] = a4.x; As[lk4 + 1][lrow] = a4.y;
        As[lk4 + 2][lrow] = a4.z; As[lk4 + 3][lrow] = a4.w;
        float4 w4 = *reinterpret_cast<const float4*>(&W[(size_t)(n0 + lrow) * ldw + k0 + lk4]);
        Ws[lk4 + 0][lrow] = w4.x; Ws[lk4 + 1][lrow] = w4.y;
        Ws[lk4 + 2][lrow] = w4.z; Ws[lk4 + 3][lrow] = w4.w;
        __syncthreads();
#pragma unroll
        for (int kk = 0; kk < BK; kk++) {
            float4 am = *reinterpret_cast<const float4*>(&As[kk][ty * 4]);
            float4 wn = *reinterpret_cast<const float4*>(&Ws[kk][tx * 4]);
            float rm[4] = {am.x, am.y, am.z, am.w};
            float rn[4] = {wn.x, wn.y, wn.z, wn.w};
#pragma unroll
            for (int i = 0; i < 4; i++)
#pragma unroll
                for (int j = 0; j < 4; j++) acc[i][j] += rm[i] * rn[j];
        }
        __syncthreads();
    }
#pragma unroll
    for (int i = 0; i < 4; i++) {
        int m = m0 + ty * 4 + i;
#pragma unroll
        for (int j = 0; j < 4; j++) {
            int n = n0 + tx * 4 + j;
            float v = acc[i][j];
            if (bias) v += bias[n];
            if (res) v += res[(size_t)m * N + n];
            if (RELU) v = fmaxf(v, 0.f);
            C[(size_t)m * N + n] = v;
        }
    }
}

// ---------------- attention: one CTA per (b,h) ----------------
__global__ void __launch_bounds__(256) attn_kernel(const float* __restrict__ qkv,
                                                   float* __restrict__ ctx) {
    int bh = blockIdx.x;
    int b = bh / H;
    int h = bh % H;
    __shared__ float Ks[T][HD + 1];
    __shared__ float Vs[T][HD + 1];
    __shared__ float Qs[8][HD];
    __shared__ float Ps[8][T];
    int tid = threadIdx.x;
    int w = tid >> 5, lane = tid & 31;
    for (int i = tid; i < T * HD; i += 256) {
        int t = i >> 6, d = i & 63;
        size_t base = ((size_t)(b * T + t)) * (3 * D) + h * HD + d;
        Ks[t][d] = qkv[base + D];
        Vs[t][d] = qkv[base + 2 * D];
    }
    __syncthreads();
    for (int r = w; r < T; r += 8) {
        size_t qb = ((size_t)(b * T + r)) * (3 * D) + h * HD;
        Qs[w][lane] = qkv[qb + lane];
        Qs[w][lane + 32] = qkv[qb + lane + 32];
        __syncwarp();
        int k0 = lane, k1 = lane + 32;
        float s0 = -1e30f, s1 = -1e30f;
        if (k0 <= r) {
            float a = 0.f;
#pragma unroll
            for (int d = 0; d < HD; d++) a += Qs[w][d] * Ks[k0][d];
            s0 = a * 0.125f;
        }
        if (k1 <= r && k1 < T) {
            float a = 0.f;
#pragma unroll
            for (int d = 0; d < HD; d++) a += Qs[w][d] * Ks[k1][d];
            s1 = a * 0.125f;
        }
        float m = fmaxf(s0, s1);
#pragma unroll
        for (int o = 16; o; o >>= 1) m = fmaxf(m, __shfl_xor_sync(0xffffffffu, m, o));
        float e0 = (k0 <= r) ? __expf(s0 - m) : 0.f;
        float e1 = (k1 <= r && k1 < T) ? __expf(s1 - m) : 0.f;
        float ssum = e0 + e1;
#pragma unroll
        for (int o = 16; o; o >>= 1) ssum += __shfl_xor_sync(0xffffffffu, ssum, o);
        float inv = 1.f / ssum;
        Ps[w][k0] = e0 * inv;
        if (k1 < T) Ps[w][k1] = e1 * inv;
        __syncwarp();
        float a0 = 0.f, a1 = 0.f;
        for (int k = 0; k <= r; k++) {
            float p = Ps[w][k];
            a0 += p * Vs[k][lane];
            a1 += p * Vs[k][lane + 32];
        }
        size_t ob = ((size_t)(b * T + r)) * D + h * HD;
        ctx[ob + lane] = a0;
        ctx[ob + lane + 32] = a1;
        __syncwarp();
    }
}

// ---------------- layernorm over D=256, one CTA per row ----------------
__global__ void __launch_bounds__(256) ln_kernel(const float* __restrict__ in,
                                                 const float* __restrict__ sc,
                                                 const float* __restrict__ bi,
                                                 float* __restrict__ out) {
    int row = blockIdx.x, tid = threadIdx.x;
    float v = in[(size_t)row * D + tid];
    float sum = v, sq = v * v;
#pragma unroll
    for (int o = 16; o; o >>= 1) {
        sum += __shfl_xor_sync(0xffffffffu, sum, o);
        sq += __shfl_xor_sync(0xffffffffu, sq, o);
    }
    __shared__ float r1[8], r2[8];
    int w = tid >> 5, lane = tid & 31;
    if (!lane) { r1[w] = sum; r2[w] = sq; }
    __syncthreads();
    if (w == 0) {
        float a = (lane < 8) ? r1[lane] : 0.f;
        float b2 = (lane < 8) ? r2[lane] : 0.f;
#pragma unroll
        for (int o = 4; o; o >>= 1) {
            a += __shfl_xor_sync(0xffffffffu, a, o);
            b2 += __shfl_xor_sync(0xffffffffu, b2, o);
        }
        if (!lane) { r1[0] = a; r2[0] = b2; }
    }
    __syncthreads();
    float mean = r1[0] * (1.f / 256.f);
    float var = r2[0] * (1.f / 256.f) - mean * mean;
    out[(size_t)row * D + tid] = (v - mean) * rsqrtf(var + EPS) * sc[tid] + bi[tid];
}

// ---------------- shift: ctxs[b,t] = (t==0)?0:x[b,t-1] ----------------
__global__ void shift_kernel(const float* __restrict__ x, float* __restrict__ ctxs) {
    int bt = blockIdx.x;
    int d = threadIdx.x;
    int t = bt % T;
    ctxs[(size_t)bt * D + d] = (t == 0) ? 0.f : x[(size_t)(bt - 1) * D + d];
}

// ---------------- u[bt,e] = sum_d cls_w[tok,d]*fus_w2[d,e]; c0 = fus_b2.w + cls_b ----
__global__ void __launch_bounds__(256) u_kernel(const int* __restrict__ tokens,
                                                const float* __restrict__ cls_w,
                                                const float* __restrict__ cls_b,
                                                const float* __restrict__ fw2,
                                                const float* __restrict__ fb2,
                                                float* __restrict__ u,
                                                float* __restrict__ c0) {
    int bt0 = blockIdx.x * 8;
    int tid = threadIdx.x;
    __shared__ float ws[8][D];
    __shared__ int toksh[8];
    if (tid < 8) toksh[tid] = tokens[bt0 + tid];
    __syncthreads();
#pragma unroll
    for (int j = 0; j < 8; j++) ws[j][tid] = cls_w[(size_t)toksh[j] * D + tid];
    __syncthreads();
    // c0 reductions
    __shared__ float red[8];
    float fb = fb2[tid];
    for (int j = 0; j < 8; j++) {
        float pv = fb * ws[j][tid];
#pragma unroll
        for (int o = 16; o; o >>= 1) pv += __shfl_xor_sync(0xffffffffu, pv, o);
        if ((tid & 31) == 0) red[tid >> 5] = pv;
        __syncthreads();
        if (tid == 0) {
            float ss = 0.f;
#pragma unroll
            for (int i = 0; i < 8; i++) ss += red[i];
            c0[bt0 + j] = ss + cls_b[toksh[j]];
        }
        __syncthreads();
    }
    // u accumulation
    float acc[8] = {};
    for (int d = 0; d < D; d++) {
        float f = fw2[(size_t)d * D + tid];
#pragma unroll
        for (int j = 0; j < 8; j++) acc[j] += ws[j][d] * f;
    }
#pragma unroll
    for (int j = 0; j < 8; j++) u[(size_t)(bt0 + j) * D + tid] = acc[j];
}

// ---------------- final fused gelu-dot + sigmoid ----------------
// grid (B, P/64), 512 threads. smem: pproj tile transposed [D][64(+pad)], cproj/u [T][D], c0[T].
constexpr int PT = 64;
constexpr int PPAD = 65;
constexpr int SMEM_FINAL = (D * PPAD + T * D + T * D + T) * 4;

__global__ void __launch_bounds__(512) final_kernel(const float* __restrict__ pproj,
                                                    const float* __restrict__ cproj,
                                                    const float* __restrict__ u,
                                                    const float* __restrict__ c0,
                                                    float* __restrict__ out) {
    extern __shared__ float sm[];
    float* pps = sm;                  // [D][PPAD]
    float* cps = pps + D * PPAD;      // [T][D]
    float* us = cps + T * D;          // [T][D]
    float* c0s = us + T * D;          // [T]
    int b = blockIdx.x;
    int p0 = blockIdx.y * PT;
    int tid = threadIdx.x;
    for (int i = tid; i < PT * D; i += 512) {
        int p = i >> 8;       // 0..63
        int e = i & 255;
        pps[e * PPAD + p] = pproj[((size_t)(b * P + p0 + p)) * D + e];
    }
    for (int i = tid; i < T * D; i += 512) {
        cps[i] = cproj[(size_t)b * T * D + i];
        us[i] = u[(size_t)b * T * D + i];
    }
    if (tid < T) c0s[tid] = c0[b * T + tid];
    __syncthreads();

    int pl = tid & 63;
    int tg = tid >> 6;  // 0..7
    float acc[5] = {};
    for (int e = 0; e < D; e++) {
        float pe = pps[e * PPAD + pl];
#pragma unroll
        for (int i = 0; i < 5; i++) {
            int t = tg + 8 * i;
            float xv = pe + cps[t * D + e];
            float g = 0.5f * xv * (1.f + erff(xv * 0.70710678118f));
            acc[i] += g * us[t * D + e];
        }
    }
    int p = p0 + pl;
#pragma unroll
    for (int i = 0; i < 5; i++) {
        int t = tg + 8 * i;
        float logit = acc[i] + c0s[t];
        out[((size_t)(b * P + p)) * T + t] = 1.f / (1.f + __expf(-logit));
    }
}

// ---------------- host ----------------
extern "C" void kernel_launch(void* const* d_in, const int* in_sizes, int n_in,
                              void* d_out, int out_size) {
    const float* patches = (const float*)d_in[0];
    const int* tokens = (const int*)d_in[1];
    const float* tok_emb = (const float*)d_in[2];
    const float* pos_emb = (const float*)d_in[3];
    const float* qkv_w = (const float*)d_in[4];
    const float* qkv_b = (const float*)d_in[5];
    const float* out_w = (const float*)d_in[6];
    const float* out_b = (const float*)d_in[7];
    const float* ln1_s = (const float*)d_in[8];
    const float* ln1_b = (const float*)d_in[9];
    const float* w1 = (const float*)d_in[10];
    const float* b1 = (const float*)d_in[11];
    const float* w2 = (const float*)d_in[12];
    const float* b2 = (const float*)d_in[13];
    const float* ln2_s = (const float*)d_in[14];
    const float* ln2_b = (const float*)d_in[15];
    const float* fus_w1 = (const float*)d_in[16];
    const float* fus_b1 = (const float*)d_in[17];
    const float* fus_w2 = (const float*)d_in[18];
    const float* fus_b2 = (const float*)d_in[19];
    const float* cls_w = (const float*)d_in[20];
    const float* cls_b = (const float*)d_in[21];
    float* out = (float*)d_out;

    float *px, *py, *pqkv, *pctx, *ph, *pctxs, *ppp, *pcp, *pu, *pc0;
    cudaGetSymbolAddress((void**)&px, g_x);
    cudaGetSymbolAddress((void**)&py, g_y);
    cudaGetSymbolAddress((void**)&pqkv, g_qkv);
    cudaGetSymbolAddress((void**)&pctx, g_ctx);
    cudaGetSymbolAddress((void**)&ph, g_h);
    cudaGetSymbolAddress((void**)&pctxs, g_ctxs);
    cudaGetSymbolAddress((void**)&ppp, g_pproj);
    cudaGetSymbolAddress((void**)&pcp, g_cproj);
    cudaGetSymbolAddress((void**)&pu, g_u);
    cudaGetSymbolAddress((void**)&pc0, g_c0);

    cudaFuncSetAttribute(final_kernel, cudaFuncAttributeMaxDynamicSharedMemorySize, SMEM_FINAL);

    const int M = B * T;  // 1280

    embed_kernel<<<M, D>>>(tokens, tok_emb, pos_emb, px);

    for (int l = 0; l < L; l++) {
        // qkv
        sgemm_kernel<false><<<dim3(3 * D / 64, M / 64), 256>>>(
            px, qkv_w + (size_t)l * 3 * D * D, qkv_b + (size_t)l * 3 * D, nullptr,
            pqkv, M, 3 * D, D, D);
        // attention
        attn_kernel<<<B * H, 256>>>(pqkv, pctx);
        // out proj + residual
        sgemm_kernel<false><<<dim3(D / 64, M / 64), 256>>>(
            pctx, out_w + (size_t)l * D * D, out_b + (size_t)l * D, px,
            py, M, D, D, D);
        ln_kernel<<<M, D>>>(py, ln1_s + (size_t)l * D, ln1_b + (size_t)l * D, px);
        // FFN
        sgemm_kernel<true><<<dim3(DFF / 64, M / 64), 256>>>(
            px, w1 + (size_t)l * DFF * D, b1 + (size_t)l * DFF, nullptr,
            ph, M, DFF, D, D);
        sgemm_kernel<false><<<dim3(D / 64, M / 64), 256>>>(
            ph, w2 + (size_t)l * D * DFF, b2 + (size_t)l * D, px,
            py, M, D, DFF, DFF);
        ln_kernel<<<M, D>>>(py, ln2_s + (size_t)l * D, ln2_b + (size_t)l * D, px);
    }

    // fusion path
    shift_kernel<<<M, D>>>(px, pctxs);
    // pproj: patches[B*P, DINO] @ wp.T, wp rows stride (DINO+D)
    sgemm_kernel<false><<<dim3(D / 64, (B * P) / 64), 256>>>(
        patches, fus_w1, nullptr, nullptr, ppp, B * P, D, DINO, DINO + D);
    // cproj: ctxs @ wc.T + fus_b1
    sgemm_kernel<false><<<dim3(D / 64, M / 64), 256>>>(
        pctxs, fus_w1 + DINO, fus_b1, nullptr, pcp, M, D, D, DINO + D);
    // u + c0
    u_kernel<<<M / 8, 256>>>(tokens, cls_w, cls_b, fus_w2, fus_b2, pu, pc0);
    // final
    final_kernel<<<dim3(B, P / PT), 512, SMEM_FINAL>>>(ppp, pcp, pu, pc0, out);
}

// round 3
// speedup vs baseline: 1.2324x; 1.2324x over previous
#include <cuda_runtime.h>
#include <cuda_bf16.h>
#include <mma.h>
#include <math.h>
#include <stdint.h>

using namespace nvcuda;

// Model dims
constexpr int B = 32, T = 40, P = 256, V = 4096, D = 256, DINO = 384, H = 4, L = 2;
constexpr int HD = 64, DFF = 1024;
constexpr float EPS = 1e-5f;

// ---------------- scratch (device globals; no allocation) ----------------
__device__ float g_x[B * T * D];
__device__ float g_y[B * T * D];
__device__ float g_qkv[B * T * 3 * D];
__device__ float g_ctx[B * T * D];
__device__ float g_h[B * T * DFF];
__device__ float g_ctxs[B * T * D];
__device__ float g_pproj[B * P * D];
__device__ float g_cproj[B * T * D];
__device__ float g_u[B * T * D];
__device__ float g_c0[B * T];

// ======================= wmma split-bf16 GEMM =======================
// C[m,n] = sum_k A[m,k] * W[n*ldw+k]  (+bias[n]) (+res[m*ldc+n0+n]) (relu)
// fp32 inputs split to bf16 hi+lo; acc = Ah*Wh + Ah*Wl + Al*Wh in fp32.
// Tiles: BM=64, BN=64, BK=64. 256 threads = 8 warps in 2x4 (m x n).
// Requires M%64==0, Ntot%64==0, K%64==0.

constexpr int BM = 64, BN = 64, BK = 64;
constexpr int LDT = 72;   // bf16 smem tile row stride (pad 8 -> conflict-free ldmatrix)
constexpr int LDC = 72;   // fp32 epilogue tile row stride

template <bool BIAS, bool RES, bool RELU>
__global__ void __launch_bounds__(256) mma_gemm(
    const float* __restrict__ A, const float* __restrict__ W,
    const float* __restrict__ bias, const float* __restrict__ res,
    float* __restrict__ C, int M, int Ntot, int K, int ldw, int ldc) {
    __shared__ __nv_bfloat16 Ah[BM * LDT];
    __shared__ __nv_bfloat16 Al[BM * LDT];
    __shared__ __nv_bfloat16 Wh[BN * LDT];
    __shared__ __nv_bfloat16 Wl[BN * LDT];

    const int tid = threadIdx.x;
    const int w = tid >> 5;
    const int wm = w >> 2;        // 0..1
    const int wn = w & 3;         // 0..3
    const int n0 = blockIdx.x * BN;
    const int m0 = blockIdx.y * BM;

    wmma::fragment<wmma::accumulator, 16, 16, 16, float> acc[2];
    wmma::fill_fragment(acc[0], 0.f);
    wmma::fill_fragment(acc[1], 0.f);

    for (int k0 = 0; k0 < K; k0 += BK) {
        // stage A: 64 rows x 64 cols fp32 -> bf16 hi/lo
        for (int i = tid; i < BM * 32; i += 256) {
            int r = i >> 5, c2 = i & 31;
            float2 v = *reinterpret_cast<const float2*>(&A[(size_t)(m0 + r) * K + k0 + c2 * 2]);
            __nv_bfloat16 hx = __float2bfloat16_rn(v.x);
            __nv_bfloat16 hy = __float2bfloat16_rn(v.y);
            __nv_bfloat16 lx = __float2bfloat16_rn(v.x - __bfloat162float(hx));
            __nv_bfloat16 ly = __float2bfloat16_rn(v.y - __bfloat162float(hy));
            int off = r * LDT + c2 * 2;
            *reinterpret_cast<__nv_bfloat162*>(&Ah[off]) = __nv_bfloat162(hx, hy);
            *reinterpret_cast<__nv_bfloat162*>(&Al[off]) = __nv_bfloat162(lx, ly);
        }
        // stage W: 64 rows (n) x 64 cols (k)
        for (int i = tid; i < BN * 32; i += 256) {
            int r = i >> 5, c2 = i & 31;
            float2 v = *reinterpret_cast<const float2*>(&W[(size_t)(n0 + r) * ldw + k0 + c2 * 2]);
            __nv_bfloat16 hx = __float2bfloat16_rn(v.x);
            __nv_bfloat16 hy = __float2bfloat16_rn(v.y);
            __nv_bfloat16 lx = __float2bfloat16_rn(v.x - __bfloat162float(hx));
            __nv_bfloat16 ly = __float2bfloat16_rn(v.y - __bfloat162float(hy));
            int off = r * LDT + c2 * 2;
            *reinterpret_cast<__nv_bfloat162*>(&Wh[off]) = __nv_bfloat162(hx, hy);
            *reinterpret_cast<__nv_bfloat162*>(&Wl[off]) = __nv_bfloat162(lx, ly);
        }
        __syncthreads();

#pragma unroll
        for (int ks = 0; ks < BK / 16; ks++) {
            wmma::fragment<wmma::matrix_b, 16, 16, 16, __nv_bfloat16, wmma::col_major> bh, bl;
            wmma::load_matrix_sync(bh, &Wh[(wn * 16) * LDT + ks * 16], LDT);
            wmma::load_matrix_sync(bl, &Wl[(wn * 16) * LDT + ks * 16], LDT);
#pragma unroll
            for (int f = 0; f < 2; f++) {
                wmma::fragment<wmma::matrix_a, 16, 16, 16, __nv_bfloat16, wmma::row_major> ah, al;
                wmma::load_matrix_sync(ah, &Ah[(wm * 32 + f * 16) * LDT + ks * 16], LDT);
                wmma::load_matrix_sync(al, &Al[(wm * 32 + f * 16) * LDT + ks * 16], LDT);
                wmma::mma_sync(acc[f], ah, bh, acc[f]);
                wmma::mma_sync(acc[f], ah, bl, acc[f]);
                wmma::mma_sync(acc[f], al, bh, acc[f]);
            }
        }
        __syncthreads();
    }

    // epilogue: store acc to smem (aliased over staging tiles), then fused ops
    float* Cs = reinterpret_cast<float*>(Ah);  // 64*72 fp32 = 18KB fits in Ah+Al (2*10368B)
    wmma::store_matrix_sync(&Cs[(wm * 32) * LDC + wn * 16], acc[0], LDC, wmma::mem_row_major);
    wmma::store_matrix_sync(&Cs[(wm * 32 + 16) * LDC + wn * 16], acc[1], LDC, wmma::mem_row_major);
    __syncthreads();

    for (int i = tid; i < BM * BN; i += 256) {
        int r = i >> 6, c = i & 63;
        int m = m0 + r, n = n0 + c;
        float v = Cs[r * LDC + c];
        if (BIAS) v += bias[n];
        if (RES) v += res[(size_t)m * ldc + n];
        if (RELU) v = fmaxf(v, 0.f);
        C[(size_t)m * ldc + n] = v;
    }
}

// ---------------- embed ----------------
__global__ void embed_kernel(const int* __restrict__ tokens,
                             const float* __restrict__ tok_emb,
                             const float* __restrict__ pos_emb,
                             float* __restrict__ x) {
    int bt = blockIdx.x;
    int d = threadIdx.x;
    int t = bt % T;
    int tok = tokens[bt];
    x[(size_t)bt * D + d] = tok_emb[(size_t)tok * D + d] + pos_emb[(size_t)t * D + d];
}

// ---------------- attention: one CTA per (b,h) ----------------
__global__ void __launch_bounds__(256) attn_kernel(const float* __restrict__ qkv,
                                                   float* __restrict__ ctx) {
    int bh = blockIdx.x;
    int b = bh / H;
    int h = bh % H;
    __shared__ float Ks[T][HD + 1];
    __shared__ float Vs[T][HD + 1];
    __shared__ float Qs[8][HD];
    __shared__ float Ps[8][T];
    int tid = threadIdx.x;
    int w = tid >> 5, lane = tid & 31;
    for (int i = tid; i < T * HD; i += 256) {
        int t = i >> 6, d = i & 63;
        size_t base = ((size_t)(b * T + t)) * (3 * D) + h * HD + d;
        Ks[t][d] = qkv[base + D];
        Vs[t][d] = qkv[base + 2 * D];
    }
    __syncthreads();
    for (int r = w; r < T; r += 8) {
        size_t qb = ((size_t)(b * T + r)) * (3 * D) + h * HD;
        Qs[w][lane] = qkv[qb + lane];
        Qs[w][lane + 32] = qkv[qb + lane + 32];
        __syncwarp();
        int k0 = lane, k1 = lane + 32;
        float s0 = -1e30f, s1 = -1e30f;
        if (k0 <= r) {
            float a = 0.f;
#pragma unroll
            for (int d = 0; d < HD; d++) a += Qs[w][d] * Ks[k0][d];
            s0 = a * 0.125f;
        }
        if (k1 <= r && k1 < T) {
            float a = 0.f;
#pragma unroll
            for (int d = 0; d < HD; d++) a += Qs[w][d] * Ks[k1][d];
            s1 = a * 0.125f;
        }
        float m = fmaxf(s0, s1);
#pragma unroll
        for (int o = 16; o; o >>= 1) m = fmaxf(m, __shfl_xor_sync(0xffffffffu, m, o));
        float e0 = (k0 <= r) ? __expf(s0 - m) : 0.f;
        float e1 = (k1 <= r && k1 < T) ? __expf(s1 - m) : 0.f;
        float ssum = e0 + e1;
#pragma unroll
        for (int o = 16; o; o >>= 1) ssum += __shfl_xor_sync(0xffffffffu, ssum, o);
        float inv = 1.f / ssum;
        Ps[w][k0] = e0 * inv;
        if (k1 < T) Ps[w][k1] = e1 * inv;
        __syncwarp();
        float a0 = 0.f, a1 = 0.f;
        for (int k = 0; k <= r; k++) {
            float p = Ps[w][k];
            a0 += p * Vs[k][lane];
            a1 += p * Vs[k][lane + 32];
        }
        size_t ob = ((size_t)(b * T + r)) * D + h * HD;
        ctx[ob + lane] = a0;
        ctx[ob + lane + 32] = a1;
        __syncwarp();
    }
}

// ---------------- layernorm over D=256, one CTA per row ----------------
__global__ void __launch_bounds__(256) ln_kernel(const float* __restrict__ in,
                                                 const float* __restrict__ sc,
                                                 const float* __restrict__ bi,
                                                 float* __restrict__ out) {
    int row = blockIdx.x, tid = threadIdx.x;
    float v = in[(size_t)row * D + tid];
    float sum = v, sq = v * v;
#pragma unroll
    for (int o = 16; o; o >>= 1) {
        sum += __shfl_xor_sync(0xffffffffu, sum, o);
        sq += __shfl_xor_sync(0xffffffffu, sq, o);
    }
    __shared__ float r1[8], r2[8];
    int w = tid >> 5, lane = tid & 31;
    if (!lane) { r1[w] = sum; r2[w] = sq; }
    __syncthreads();
    if (w == 0) {
        float a = (lane < 8) ? r1[lane] : 0.f;
        float b2 = (lane < 8) ? r2[lane] : 0.f;
#pragma unroll
        for (int o = 4; o; o >>= 1) {
            a += __shfl_xor_sync(0xffffffffu, a, o);
            b2 += __shfl_xor_sync(0xffffffffu, b2, o);
        }
        if (!lane) { r1[0] = a; r2[0] = b2; }
    }
    __syncthreads();
    float mean = r1[0] * (1.f / 256.f);
    float var = r2[0] * (1.f / 256.f) - mean * mean;
    out[(size_t)row * D + tid] = (v - mean) * rsqrtf(var + EPS) * sc[tid] + bi[tid];
}

// ---------------- shift ----------------
__global__ void shift_kernel(const float* __restrict__ x, float* __restrict__ ctxs) {
    int bt = blockIdx.x;
    int d = threadIdx.x;
    int t = bt % T;
    ctxs[(size_t)bt * D + d] = (t == 0) ? 0.f : x[(size_t)(bt - 1) * D + d];
}

// ---------------- u[bt,e] = sum_d cls_w[tok,d]*fus_w2[d,e]; c0 = fus_b2.w + cls_b ----
__global__ void __launch_bounds__(256) u_kernel(const int* __restrict__ tokens,
                                                const float* __restrict__ cls_w,
                                                const float* __restrict__ cls_b,
                                                const float* __restrict__ fw2,
                                                const float* __restrict__ fb2,
                                                float* __restrict__ u,
                                                float* __restrict__ c0) {
    int bt0 = blockIdx.x * 8;
    int tid = threadIdx.x;
    __shared__ float ws[8][D];
    __shared__ int toksh[8];
    if (tid < 8) toksh[tid] = tokens[bt0 + tid];
    __syncthreads();
#pragma unroll
    for (int j = 0; j < 8; j++) ws[j][tid] = cls_w[(size_t)toksh[j] * D + tid];
    __syncthreads();
    __shared__ float red[8];
    float fb = fb2[tid];
    for (int j = 0; j < 8; j++) {
        float pv = fb * ws[j][tid];
#pragma unroll
        for (int o = 16; o; o >>= 1) pv += __shfl_xor_sync(0xffffffffu, pv, o);
        if ((tid & 31) == 0) red[tid >> 5] = pv;
        __syncthreads();
        if (tid == 0) {
            float ss = 0.f;
#pragma unroll
            for (int i = 0; i < 8; i++) ss += red[i];
            c0[bt0 + j] = ss + cls_b[toksh[j]];
        }
        __syncthreads();
    }
    float acc[8] = {};
    for (int d = 0; d < D; d++) {
        float f = fw2[(size_t)d * D + tid];
#pragma unroll
        for (int j = 0; j < 8; j++) acc[j] += ws[j][d] * f;
    }
#pragma unroll
    for (int j = 0; j < 8; j++) u[(size_t)(bt0 + j) * D + tid] = acc[j];
}

// ---------------- final fused gelu-dot + sigmoid ----------------
constexpr int PT = 64;
constexpr int PPAD = 65;
constexpr int SMEM_FINAL = (D * PPAD + T * D + T * D + T) * 4;

__global__ void __launch_bounds__(512) final_kernel(const float* __restrict__ pproj,
                                                    const float* __restrict__ cproj,
                                                    const float* __restrict__ u,
                                                    const float* __restrict__ c0,
                                                    float* __restrict__ out) {
    extern __shared__ float sm[];
    float* pps = sm;                  // [D][PPAD]
    float* cps = pps + D * PPAD;      // [T][D]
    float* us = cps + T * D;          // [T][D]
    float* c0s = us + T * D;          // [T]
    int b = blockIdx.x;
    int p0 = blockIdx.y * PT;
    int tid = threadIdx.x;
    for (int i = tid; i < PT * D; i += 512) {
        int p = i >> 8;
        int e = i & 255;
        pps[e * PPAD + p] = pproj[((size_t)(b * P + p0 + p)) * D + e];
    }
    for (int i = tid; i < T * D; i += 512) {
        cps[i] = cproj[(size_t)b * T * D + i];
        us[i] = u[(size_t)b * T * D + i];
    }
    if (tid < T) c0s[tid] = c0[b * T + tid];
    __syncthreads();

    int pl = tid & 63;
    int tg = tid >> 6;
    float acc[5] = {};
    for (int e = 0; e < D; e++) {
        float pe = pps[e * PPAD + pl];
#pragma unroll
        for (int i = 0; i < 5; i++) {
            int t = tg + 8 * i;
            float xv = pe + cps[t * D + e];
            float g = 0.5f * xv * (1.f + erff(xv * 0.70710678118f));
            acc[i] += g * us[t * D + e];
        }
    }
    int p = p0 + pl;
#pragma unroll
    for (int i = 0; i < 5; i++) {
        int t = tg + 8 * i;
        float logit = acc[i] + c0s[t];
        out[((size_t)(b * P + p)) * T + t] = 1.f / (1.f + __expf(-logit));
    }
}

// ---------------- host ----------------
extern "C" void kernel_launch(void* const* d_in, const int* in_sizes, int n_in,
                              void* d_out, int out_size) {
    const float* patches = (const float*)d_in[0];
    const int* tokens = (const int*)d_in[1];
    const float* tok_emb = (const float*)d_in[2];
    const float* pos_emb = (const float*)d_in[3];
    const float* qkv_w = (const float*)d_in[4];
    const float* qkv_b = (const float*)d_in[5];
    const float* out_w = (const float*)d_in[6];
    const float* out_b = (const float*)d_in[7];
    const float* ln1_s = (const float*)d_in[8];
    const float* ln1_b = (const float*)d_in[9];
    const float* w1 = (const float*)d_in[10];
    const float* b1 = (const float*)d_in[11];
    const float* w2 = (const float*)d_in[12];
    const float* b2 = (const float*)d_in[13];
    const float* ln2_s = (const float*)d_in[14];
    const float* ln2_b = (const float*)d_in[15];
    const float* fus_w1 = (const float*)d_in[16];
    const float* fus_b1 = (const float*)d_in[17];
    const float* fus_w2 = (const float*)d_in[18];
    const float* fus_b2 = (const float*)d_in[19];
    const float* cls_w = (const float*)d_in[20];
    const float* cls_b = (const float*)d_in[21];
    float* out = (float*)d_out;

    float *px, *py, *pqkv, *pctx, *ph, *pctxs, *ppp, *pcp, *pu, *pc0;
    cudaGetSymbolAddress((void**)&px, g_x);
    cudaGetSymbolAddress((void**)&py, g_y);
    cudaGetSymbolAddress((void**)&pqkv, g_qkv);
    cudaGetSymbolAddress((void**)&pctx, g_ctx);
    cudaGetSymbolAddress((void**)&ph, g_h);
    cudaGetSymbolAddress((void**)&pctxs, g_ctxs);
    cudaGetSymbolAddress((void**)&ppp, g_pproj);
    cudaGetSymbolAddress((void**)&pcp, g_cproj);
    cudaGetSymbolAddress((void**)&pu, g_u);
    cudaGetSymbolAddress((void**)&pc0, g_c0);

    cudaFuncSetAttribute(final_kernel, cudaFuncAttributeMaxDynamicSharedMemorySize, SMEM_FINAL);

    const int M = B * T;  // 1280

    embed_kernel<<<M, D>>>(tokens, tok_emb, pos_emb, px);

    for (int l = 0; l < L; l++) {
        // qkv = x @ qkv_w[l]^T + b : [1280, 768]
        mma_gemm<true, false, false><<<dim3(3 * D / BN, M / BM), 256>>>(
            px, qkv_w + (size_t)l * 3 * D * D, qkv_b + (size_t)l * 3 * D,
            nullptr, pqkv, M, 3 * D, D, D, 3 * D);
        attn_kernel<<<B * H, 256>>>(pqkv, pctx);
        // y = x + ctx @ out_w^T + out_b ; x = LN(y)
        mma_gemm<true, true, false><<<dim3(D / BN, M / BM), 256>>>(
            pctx, out_w + (size_t)l * D * D, out_b + (size_t)l * D,
            px, py, M, D, D, D, D);
        ln_kernel<<<M, D>>>(py, ln1_s + (size_t)l * D, ln1_b + (size_t)l * D, px);
        // h = relu(x @ w1^T + b1) : [1280, 1024]
        mma_gemm<true, false, true><<<dim3(DFF / BN, M / BM), 256>>>(
            px, w1 + (size_t)l * DFF * D, b1 + (size_t)l * DFF,
            nullptr, ph, M, DFF, D, D, DFF);
        // y = x + h @ w2^T + b2 ; x = LN(y)
        mma_gemm<true, true, false><<<dim3(D / BN, M / BM), 256>>>(
            ph, w2 + (size_t)l * D * DFF, b2 + (size_t)l * D,
            px, py, M, D, DFF, DFF, D);
        ln_kernel<<<M, D>>>(py, ln2_s + (size_t)l * D, ln2_b + (size_t)l * D, px);
    }

    // fusion path
    shift_kernel<<<M, D>>>(px, pctxs);
    // pproj = patches @ wp^T : [8192, 256], wp rows stride DINO+D
    mma_gemm<false, false, false><<<dim3(D / BN, (B * P) / BM), 256>>>(
        patches, fus_w1, nullptr, nullptr, ppp, B * P, D, DINO, DINO + D, D);
    // cproj = ctxs @ wc^T + fus_b1
    mma_gemm<true, false, false><<<dim3(D / BN, M / BM), 256>>>(
        pctxs, fus_w1 + DINO, fus_b1, nullptr, pcp, M, D, D, DINO + D, D);
    u_kernel<<<M / 8, 256>>>(tokens, cls_w, cls_b, fus_w2, fus_b2, pu, pc0);
    final_kernel<<<dim3(B, P / PT), 512, SMEM_FINAL>>>(ppp, pcp, pu, pc0, out);
}

// round 4
// speedup vs baseline: 1.9627x; 1.5926x over previous
#include <cuda_runtime.h>
#include <cuda_bf16.h>
#include <mma.h>
#include <stdint.h>

using namespace nvcuda;

// Model dims
constexpr int B = 32, T = 40, P = 256, V = 4096, D = 256, DINO = 384, H = 4, L = 2;
constexpr int HD = 64, DFF = 1024;
constexpr float EPS = 1e-5f;
constexpr int M_ENC = B * T;  // 1280

// ---------------- fp32 scratch ----------------
__device__ float g_x[M_ENC * D];
__device__ float g_y[M_ENC * D];
__device__ float g_qkv[M_ENC * 3 * D];
__device__ float g_pproj[B * P * D];
__device__ float g_cproj[M_ENC * D];
__device__ float g_u[M_ENC * D];
__device__ float g_c0[M_ENC];

// ---------------- bf16 hi/lo scratch ----------------
__device__ __nv_bfloat16 g_xh[M_ENC * D], g_xl[M_ENC * D];
__device__ __nv_bfloat16 g_ctxh[M_ENC * D], g_ctxl[M_ENC * D];
__device__ __nv_bfloat16 g_hh[M_ENC * DFF], g_hl2[M_ENC * DFF];
__device__ __nv_bfloat16 g_ph[B * P * DINO], g_pl[B * P * DINO];
__device__ __nv_bfloat16 g_qkvwh[L * 3 * D * D], g_qkvwl[L * 3 * D * D];
__device__ __nv_bfloat16 g_outwh[L * D * D], g_outwl[L * D * D];
__device__ __nv_bfloat16 g_w1h[L * DFF * D], g_w1l[L * DFF * D];
__device__ __nv_bfloat16 g_w2h[L * D * DFF], g_w2l[L * D * DFF];
__device__ __nv_bfloat16 g_fw1h[D * (DINO + D)], g_fw1l[D * (DINO + D)];

// ---------------- helpers ----------------
__device__ __forceinline__ uint32_t smem_u32(const void* p) {
    uint32_t a;
    asm("{ .reg .u64 t; cvta.to.shared.u64 t, %1; cvt.u32.u64 %0, t; }" : "=r"(a) : "l"(p));
    return a;
}
__device__ __forceinline__ void cpa16(uint32_t dst, const void* src, int sz) {
    asm volatile("cp.async.cg.shared.global [%0], [%1], 16, %2;" :: "r"(dst), "l"(src), "r"(sz));
}
__device__ __forceinline__ void cpa_commit() { asm volatile("cp.async.commit_group;"); }

__device__ __forceinline__ float gelu_f(float x) {
    float x2 = x * x;
    float targ = 0.7978845608f * x * fmaf(0.044715f, x2, 1.f);
    float th;
    asm("tanh.approx.f32 %0, %1;" : "=f"(th) : "f"(targ));
    return 0.5f * x * (1.f + th);
}

__device__ __forceinline__ void split4(float4 v, __nv_bfloat16* dh, __nv_bfloat16* dl, size_t off) {
    __nv_bfloat16 h0 = __float2bfloat16_rn(v.x), h1 = __float2bfloat16_rn(v.y);
    __nv_bfloat16 h2 = __float2bfloat16_rn(v.z), h3 = __float2bfloat16_rn(v.w);
    *reinterpret_cast<__nv_bfloat162*>(&dh[off]) = __nv_bfloat162(h0, h1);
    *reinterpret_cast<__nv_bfloat162*>(&dh[off + 2]) = __nv_bfloat162(h2, h3);
    __nv_bfloat16 l0 = __float2bfloat16_rn(v.x - __bfloat162float(h0));
    __nv_bfloat16 l1 = __float2bfloat16_rn(v.y - __bfloat162float(h1));
    __nv_bfloat16 l2 = __float2bfloat16_rn(v.z - __bfloat162float(h2));
    __nv_bfloat16 l3 = __float2bfloat16_rn(v.w - __bfloat162float(h3));
    *reinterpret_cast<__nv_bfloat162*>(&dl[off]) = __nv_bfloat162(l0, l1);
    *reinterpret_cast<__nv_bfloat162*>(&dl[off + 2]) = __nv_bfloat162(l2, l3);
}

// ---------------- prep: split all weights/patches to bf16 hi/lo + embed ----------------
__global__ void __launch_bounds__(256) prep_kernel(
    const float* __restrict__ qkv_w, const float* __restrict__ out_w,
    const float* __restrict__ w1, const float* __restrict__ w2,
    const float* __restrict__ fus_w1, const float* __restrict__ patches,
    const int* __restrict__ tokens, const float* __restrict__ tok_emb,
    const float* __restrict__ pos_emb) {
    constexpr int S1 = L * 3 * D * D / 4;
    constexpr int S2 = L * D * D / 4;
    constexpr int S3 = L * DFF * D / 4;
    constexpr int S4 = L * D * DFF / 4;
    constexpr int S5 = D * (DINO + D) / 4;
    constexpr int S6 = B * P * DINO / 4;
    constexpr int S7 = M_ENC * D / 4;
    constexpr int TOT = S1 + S2 + S3 + S4 + S5 + S6 + S7;
    for (int i = blockIdx.x * blockDim.x + threadIdx.x; i < TOT; i += gridDim.x * blockDim.x) {
        int j = i;
        const float* src;
        __nv_bfloat16 *dh, *dl;
        if (j < S1) { src = qkv_w; dh = g_qkvwh; dl = g_qkvwl; }
        else if ((j -= S1) < S2) { src = out_w; dh = g_outwh; dl = g_outwl; }
        else if ((j -= S2) < S3) { src = w1; dh = g_w1h; dl = g_w1l; }
        else if ((j -= S3) < S4) { src = w2; dh = g_w2h; dl = g_w2l; }
        else if ((j -= S4) < S5) { src = fus_w1; dh = g_fw1h; dl = g_fw1l; }
        else if ((j -= S5) < S6) { src = patches; dh = g_ph; dl = g_pl; }
        else {
            j -= S6;
            int bt = (j * 4) >> 8;
            int d0 = (j * 4) & 255;
            int t = bt % T;
            float4 te = *reinterpret_cast<const float4*>(&tok_emb[(size_t)tokens[bt] * D + d0]);
            float4 pe = *reinterpret_cast<const float4*>(&pos_emb[(size_t)t * D + d0]);
            float4 v = make_float4(te.x + pe.x, te.y + pe.y, te.z + pe.z, te.w + pe.w);
            *reinterpret_cast<float4*>(&g_x[(size_t)j * 4]) = v;
            split4(v, g_xh, g_xl, (size_t)j * 4);
            continue;
        }
        float4 v = *reinterpret_cast<const float4*>(&src[(size_t)j * 4]);
        split4(v, dh, dl, (size_t)j * 4);
    }
}

// ======================= bf16 split GEMM, cp.async double-buffered =======================
// C[m,n] = sum_k A[m,k]*W[n*ldw+k] via (Ah+Al)(Wh+Wl) dropping Al*Wl.
// Tiles BM=BN=BK=64. 256 threads = 8 warps (2m x 4n).
constexpr int BM = 64, BN = 64, BK = 64;
constexpr int LDTE = 72;               // elements (144B rows, conflict-free ldmatrix)
constexpr int TILEB = 64 * LDTE * 2;   // 9216 bytes per tile-buffer
constexpr int GEMM_SMEM = 8 * TILEB;   // 2 bufs x 4 arrays = 73728 B

template <bool BIAS, bool RES, bool RELU, bool EMIT32, bool EMITHL, bool SHIFT>
__global__ void __launch_bounds__(256) gemm_bf16(
    const __nv_bfloat16* __restrict__ Ah, const __nv_bfloat16* __restrict__ Al, int lda,
    const __nv_bfloat16* __restrict__ Wh, const __nv_bfloat16* __restrict__ Wl, int ldw,
    const float* __restrict__ bias, const float* __restrict__ res,
    float* __restrict__ C32, __nv_bfloat16* __restrict__ Ch, __nv_bfloat16* __restrict__ Cl,
    int ldc, int K) {
    extern __shared__ char sm[];
    const int tid = threadIdx.x;
    const int n0 = blockIdx.x * BN;
    const int m0 = blockIdx.y * BM;
    const int nchunk = K / BK;
    const uint32_t sb0 = smem_u32(sm);

    auto stage = [&](int c) {
        const int buf = c & 1;
        const uint32_t sbase = sb0 + buf * 4 * TILEB;
        const int k0 = c * BK;
#pragma unroll
        for (int g = 0; g < 2; g++) {
            int gi = tid + g * 256;
            int row = gi >> 3, c16 = gi & 7;
            uint32_t soff = row * 144 + c16 * 16;
            int am = m0 + row;
            size_t aoff;
            int sz = 16;
            if (SHIFT) {
                int t = am % T;
                if (t == 0) { sz = 0; aoff = (size_t)am * lda + k0 + c16 * 8; }
                else aoff = (size_t)(am - 1) * lda + k0 + c16 * 8;
            } else {
                aoff = (size_t)am * lda + k0 + c16 * 8;
            }
            cpa16(sbase + 0 * TILEB + soff, Ah + aoff, sz);
            cpa16(sbase + 1 * TILEB + soff, Al + aoff, sz);
            size_t woff = (size_t)(n0 + row) * ldw + k0 + c16 * 8;
            cpa16(sbase + 2 * TILEB + soff, Wh + woff, 16);
            cpa16(sbase + 3 * TILEB + soff, Wl + woff, 16);
        }
        cpa_commit();
    };

    stage(0);

    const int w = tid >> 5;
    const int wm = w >> 2;   // 0..1
    const int wn = w & 3;    // 0..3

    wmma::fragment<wmma::accumulator, 16, 16, 16, float> acc[2];
    wmma::fill_fragment(acc[0], 0.f);
    wmma::fill_fragment(acc[1], 0.f);

    for (int c = 0; c < nchunk; c++) {
        if (c + 1 < nchunk) {
            stage(c + 1);
            asm volatile("cp.async.wait_group 1;");
        } else {
            asm volatile("cp.async.wait_group 0;");
        }
        __syncthreads();
        char* bb = sm + (c & 1) * 4 * TILEB;
        const __nv_bfloat16* tAh = reinterpret_cast<const __nv_bfloat16*>(bb);
        const __nv_bfloat16* tAl = reinterpret_cast<const __nv_bfloat16*>(bb + TILEB);
        const __nv_bfloat16* tWh = reinterpret_cast<const __nv_bfloat16*>(bb + 2 * TILEB);
        const __nv_bfloat16* tWl = reinterpret_cast<const __nv_bfloat16*>(bb + 3 * TILEB);
#pragma unroll
        for (int ks = 0; ks < 4; ks++) {
            wmma::fragment<wmma::matrix_b, 16, 16, 16, __nv_bfloat16, wmma::col_major> bh, bl;
            wmma::load_matrix_sync(bh, &tWh[(wn * 16) * LDTE + ks * 16], LDTE);
            wmma::load_matrix_sync(bl, &tWl[(wn * 16) * LDTE + ks * 16], LDTE);
#pragma unroll
            for (int f = 0; f < 2; f++) {
                wmma::fragment<wmma::matrix_a, 16, 16, 16, __nv_bfloat16, wmma::row_major> ah, al;
                wmma::load_matrix_sync(ah, &tAh[(wm * 32 + f * 16) * LDTE + ks * 16], LDTE);
                wmma::load_matrix_sync(al, &tAl[(wm * 32 + f * 16) * LDTE + ks * 16], LDTE);
                wmma::mma_sync(acc[f], ah, bh, acc[f]);
                wmma::mma_sync(acc[f], ah, bl, acc[f]);
                wmma::mma_sync(acc[f], al, bh, acc[f]);
            }
        }
        __syncthreads();
    }

    // epilogue via smem (aliases buffer 0)
    float* Cs = reinterpret_cast<float*>(sm);  // 64*72*4 = 18432 B
    wmma::store_matrix_sync(&Cs[(wm * 32) * LDTE + wn * 16], acc[0], LDTE, wmma::mem_row_major);
    wmma::store_matrix_sync(&Cs[(wm * 32 + 16) * LDTE + wn * 16], acc[1], LDTE, wmma::mem_row_major);
    __syncthreads();

#pragma unroll
    for (int i = tid; i < BM * BN; i += 256) {
        int r = i >> 6, cc = i & 63;
        int m = m0 + r, n = n0 + cc;
        float v = Cs[r * LDTE + cc];
        if (BIAS) v += bias[n];
        if (RES) v += res[(size_t)m * ldc + n];
        if (RELU) v = fmaxf(v, 0.f);
        if (EMIT32) C32[(size_t)m * ldc + n] = v;
        if (EMITHL) {
            __nv_bfloat16 hv = __float2bfloat16_rn(v);
            Ch[(size_t)m * ldc + n] = hv;
            Cl[(size_t)m * ldc + n] = __float2bfloat16_rn(v - __bfloat162float(hv));
        }
    }
}

// ---------------- attention: one CTA per (b,h); emits ctx hi/lo ----------------
__global__ void __launch_bounds__(256) attn_kernel(const float* __restrict__ qkv,
                                                   __nv_bfloat16* __restrict__ ctxh,
                                                   __nv_bfloat16* __restrict__ ctxl) {
    int bh = blockIdx.x;
    int b = bh / H;
    int h = bh % H;
    __shared__ float Ks[T][HD + 1];
    __shared__ float Vs[T][HD + 1];
    __shared__ float Qs[8][HD];
    __shared__ float Ps[8][T];
    int tid = threadIdx.x;
    int w = tid >> 5, lane = tid & 31;
    for (int i = tid; i < T * HD; i += 256) {
        int t = i >> 6, d = i & 63;
        size_t base = ((size_t)(b * T + t)) * (3 * D) + h * HD + d;
        Ks[t][d] = qkv[base + D];
        Vs[t][d] = qkv[base + 2 * D];
    }
    __syncthreads();
    for (int r = w; r < T; r += 8) {
        size_t qb = ((size_t)(b * T + r)) * (3 * D) + h * HD;
        Qs[w][lane] = qkv[qb + lane];
        Qs[w][lane + 32] = qkv[qb + lane + 32];
        __syncwarp();
        int k0 = lane, k1 = lane + 32;
        float s0 = -1e30f, s1 = -1e30f;
        if (k0 <= r) {
            float a = 0.f;
#pragma unroll
            for (int d = 0; d < HD; d++) a += Qs[w][d] * Ks[k0][d];
            s0 = a * 0.125f;
        }
        if (k1 <= r && k1 < T) {
            float a = 0.f;
#pragma unroll
            for (int d = 0; d < HD; d++) a += Qs[w][d] * Ks[k1][d];
            s1 = a * 0.125f;
        }
        float m = fmaxf(s0, s1);
#pragma unroll
        for (int o = 16; o; o >>= 1) m = fmaxf(m, __shfl_xor_sync(0xffffffffu, m, o));
        float e0 = (k0 <= r) ? __expf(s0 - m) : 0.f;
        float e1 = (k1 <= r && k1 < T) ? __expf(s1 - m) : 0.f;
        float ssum = e0 + e1;
#pragma unroll
        for (int o = 16; o; o >>= 1) ssum += __shfl_xor_sync(0xffffffffu, ssum, o);
        float inv = 1.f / ssum;
        Ps[w][k0] = e0 * inv;
        if (k1 < T) Ps[w][k1] = e1 * inv;
        __syncwarp();
        float a0 = 0.f, a1 = 0.f;
        for (int k = 0; k <= r; k++) {
            float p = Ps[w][k];
            a0 += p * Vs[k][lane];
            a1 += p * Vs[k][lane + 32];
        }
        size_t ob = ((size_t)(b * T + r)) * D + h * HD;
        __nv_bfloat16 h0 = __float2bfloat16_rn(a0);
        __nv_bfloat16 h1 = __float2bfloat16_rn(a1);
        ctxh[ob + lane] = h0;
        ctxh[ob + lane + 32] = h1;
        ctxl[ob + lane] = __float2bfloat16_rn(a0 - __bfloat162float(h0));
        ctxl[ob + lane + 32] = __float2bfloat16_rn(a1 - __bfloat162float(h1));
        __syncwarp();
    }
}

// ---------------- layernorm over D=256 -> fp32 + hi/lo ----------------
__global__ void __launch_bounds__(256) ln_kernel(const float* __restrict__ in,
                                                 const float* __restrict__ sc,
                                                 const float* __restrict__ bi,
                                                 float* __restrict__ out32,
                                                 __nv_bfloat16* __restrict__ outh,
                                                 __nv_bfloat16* __restrict__ outl) {
    int row = blockIdx.x, tid = threadIdx.x;
    float v = in[(size_t)row * D + tid];
    float sum = v, sq = v * v;
#pragma unroll
    for (int o = 16; o; o >>= 1) {
        sum += __shfl_xor_sync(0xffffffffu, sum, o);
        sq += __shfl_xor_sync(0xffffffffu, sq, o);
    }
    __shared__ float r1[8], r2[8];
    int w = tid >> 5, lane = tid & 31;
    if (!lane) { r1[w] = sum; r2[w] = sq; }
    __syncthreads();
    if (w == 0) {
        float a = (lane < 8) ? r1[lane] : 0.f;
        float b2 = (lane < 8) ? r2[lane] : 0.f;
#pragma unroll
        for (int o = 4; o; o >>= 1) {
            a += __shfl_xor_sync(0xffffffffu, a, o);
            b2 += __shfl_xor_sync(0xffffffffu, b2, o);
        }
        if (!lane) { r1[0] = a; r2[0] = b2; }
    }
    __syncthreads();
    float mean = r1[0] * (1.f / 256.f);
    float var = r2[0] * (1.f / 256.f) - mean * mean;
    float o = (v - mean) * rsqrtf(var + EPS) * sc[tid] + bi[tid];
    size_t idx = (size_t)row * D + tid;
    out32[idx] = o;
    __nv_bfloat16 h = __float2bfloat16_rn(o);
    outh[idx] = h;
    outl[idx] = __float2bfloat16_rn(o - __bfloat162float(h));
}

// ---------------- u[bt,e] = sum_d cls_w[tok,d]*fus_w2[d,e]; c0 = fus_b2.w + cls_b ----
__global__ void __launch_bounds__(256) u_kernel(const int* __restrict__ tokens,
                                                const float* __restrict__ cls_w,
                                                const float* __restrict__ cls_b,
                                                const float* __restrict__ fw2,
                                                const float* __restrict__ fb2,
                                                float* __restrict__ u,
                                                float* __restrict__ c0) {
    int bt0 = blockIdx.x * 8;
    int tid = threadIdx.x, w = tid >> 5, lane = tid & 31;
    __shared__ float ws[8][D];
    __shared__ int toksh[8];
    if (tid < 8) toksh[tid] = tokens[bt0 + tid];
    __syncthreads();
#pragma unroll
    for (int j = 0; j < 8; j++) ws[j][tid] = cls_w[(size_t)toksh[j] * D + tid];
    __syncthreads();
    // c0: warp w handles row j=w
    {
        float s = 0.f;
        for (int d = lane; d < D; d += 32) s += fb2[d] * ws[w][d];
#pragma unroll
        for (int o = 16; o; o >>= 1) s += __shfl_xor_sync(0xffffffffu, s, o);
        if (!lane) c0[bt0 + w] = s + cls_b[toksh[w]];
    }
    float acc[8] = {};
    for (int d = 0; d < D; d++) {
        float f = fw2[(size_t)d * D + tid];
#pragma unroll
        for (int j = 0; j < 8; j++) acc[j] += ws[j][d] * f;
    }
#pragma unroll
    for (int j = 0; j < 8; j++) u[(size_t)(bt0 + j) * D + tid] = acc[j];
}

// ---------------- final fused gelu-dot + sigmoid ----------------
constexpr int PT = 64;
constexpr int PPAD = 65;
constexpr int SMEM_FINAL = (D * PPAD + T * D + T * D + T) * 4;

__global__ void __launch_bounds__(512) final_kernel(const float* __restrict__ pproj,
                                                    const float* __restrict__ cproj,
                                                    const float* __restrict__ u,
                                                    const float* __restrict__ c0,
                                                    float* __restrict__ out) {
    extern __shared__ float smf[];
    float* pps = smf;                 // [D][PPAD]
    float* cps = pps + D * PPAD;      // [T][D]
    float* us = cps + T * D;          // [T][D]
    float* c0s = us + T * D;          // [T]
    int b = blockIdx.x;
    int p0 = blockIdx.y * PT;
    int tid = threadIdx.x;
    for (int i = tid; i < PT * D; i += 512) {
        int p = i >> 8;
        int e = i & 255;
        pps[e * PPAD + p] = pproj[((size_t)(b * P + p0 + p)) * D + e];
    }
    for (int i = tid; i < T * D; i += 512) {
        cps[i] = cproj[(size_t)b * T * D + i];
        us[i] = u[(size_t)b * T * D + i];
    }
    if (tid < T) c0s[tid] = c0[b * T + tid];
    __syncthreads();

    int pl = tid & 63;
    int tg = tid >> 6;
    float acc[5] = {};
    for (int e = 0; e < D; e += 2) {
        float pe0 = pps[e * PPAD + pl];
        float pe1 = pps[(e + 1) * PPAD + pl];
#pragma unroll
        for (int i = 0; i < 5; i++) {
            int t = tg + 8 * i;
            float2 cp = *reinterpret_cast<const float2*>(&cps[t * D + e]);
            float2 uu = *reinterpret_cast<const float2*>(&us[t * D + e]);
            float x0 = pe0 + cp.x;
            float x1 = pe1 + cp.y;
            acc[i] += gelu_f(x0) * uu.x + gelu_f(x1) * uu.y;
        }
    }
    int p = p0 + pl;
#pragma unroll
    for (int i = 0; i < 5; i++) {
        int t = tg + 8 * i;
        float logit = acc[i] + c0s[t];
        out[((size_t)(b * P + p)) * T + t] = 1.f / (1.f + __expf(-logit));
    }
}

// ---------------- host ----------------
extern "C" void kernel_launch(void* const* d_in, const int* in_sizes, int n_in,
                              void* d_out, int out_size) {
    const float* patches = (const float*)d_in[0];
    const int* tokens = (const int*)d_in[1];
    const float* tok_emb = (const float*)d_in[2];
    const float* pos_emb = (const float*)d_in[3];
    const float* qkv_w = (const float*)d_in[4];
    const float* qkv_b = (const float*)d_in[5];
    const float* out_w = (const float*)d_in[6];
    const float* out_b = (const float*)d_in[7];
    const float* ln1_s = (const float*)d_in[8];
    const float* ln1_b = (const float*)d_in[9];
    const float* w1 = (const float*)d_in[10];
    const float* b1 = (const float*)d_in[11];
    const float* w2 = (const float*)d_in[12];
    const float* b2 = (const float*)d_in[13];
    const float* ln2_s = (const float*)d_in[14];
    const float* ln2_b = (const float*)d_in[15];
    const float* fus_w1 = (const float*)d_in[16];
    const float* fus_b1 = (const float*)d_in[17];
    const float* fus_w2 = (const float*)d_in[18];
    const float* fus_b2 = (const float*)d_in[19];
    const float* cls_w = (const float*)d_in[20];
    const float* cls_b = (const float*)d_in[21];
    float* out = (float*)d_out;

    float *px, *py, *pqkv, *ppp, *pcp, *pu, *pc0;
    cudaGetSymbolAddress((void**)&px, g_x);
    cudaGetSymbolAddress((void**)&py, g_y);
    cudaGetSymbolAddress((void**)&pqkv, g_qkv);
    cudaGetSymbolAddress((void**)&ppp, g_pproj);
    cudaGetSymbolAddress((void**)&pcp, g_cproj);
    cudaGetSymbolAddress((void**)&pu, g_u);
    cudaGetSymbolAddress((void**)&pc0, g_c0);

    __nv_bfloat16 *pxh, *pxl, *pch, *pcl, *phh, *phl, *pph, *ppl;
    __nv_bfloat16 *pqwh, *pqwl, *powh, *powl, *pw1h, *pw1l, *pw2h, *pw2l, *pfwh, *pfwl;
    cudaGetSymbolAddress((void**)&pxh, g_xh);
    cudaGetSymbolAddress((void**)&pxl, g_xl);
    cudaGetSymbolAddress((void**)&pch, g_ctxh);
    cudaGetSymbolAddress((void**)&pcl, g_ctxl);
    cudaGetSymbolAddress((void**)&phh, g_hh);
    cudaGetSymbolAddress((void**)&phl, g_hl2);
    cudaGetSymbolAddress((void**)&pph, g_ph);
    cudaGetSymbolAddress((void**)&ppl, g_pl);
    cudaGetSymbolAddress((void**)&pqwh, g_qkvwh);
    cudaGetSymbolAddress((void**)&pqwl, g_qkvwl);
    cudaGetSymbolAddress((void**)&powh, g_outwh);
    cudaGetSymbolAddress((void**)&powl, g_outwl);
    cudaGetSymbolAddress((void**)&pw1h, g_w1h);
    cudaGetSymbolAddress((void**)&pw1l, g_w1l);
    cudaGetSymbolAddress((void**)&pw2h, g_w2h);
    cudaGetSymbolAddress((void**)&pw2l, g_w2l);
    cudaGetSymbolAddress((void**)&pfwh, g_fw1h);
    cudaGetSymbolAddress((void**)&pfwl, g_fw1l);

    cudaFuncSetAttribute(final_kernel, cudaFuncAttributeMaxDynamicSharedMemorySize, SMEM_FINAL);
    cudaFuncSetAttribute(gemm_bf16<true, false, false, true, false, false>, cudaFuncAttributeMaxDynamicSharedMemorySize, GEMM_SMEM);
    cudaFuncSetAttribute(gemm_bf16<true, true, false, true, false, false>, cudaFuncAttributeMaxDynamicSharedMemorySize, GEMM_SMEM);
    cudaFuncSetAttribute(gemm_bf16<true, false, true, false, true, false>, cudaFuncAttributeMaxDynamicSharedMemorySize, GEMM_SMEM);
    cudaFuncSetAttribute(gemm_bf16<false, false, false, true, false, false>, cudaFuncAttributeMaxDynamicSharedMemorySize, GEMM_SMEM);
    cudaFuncSetAttribute(gemm_bf16<true, false, false, true, false, true>, cudaFuncAttributeMaxDynamicSharedMemorySize, GEMM_SMEM);

    // prep: weight/patches split + embed
    prep_kernel<<<1024, 256>>>(qkv_w, out_w, w1, w2, fus_w1, patches, tokens, tok_emb, pos_emb);

    // pproj = patches @ wp^T (independent of encoder)
    gemm_bf16<false, false, false, true, false, false><<<dim3(D / BN, B * P / BM), 256, GEMM_SMEM>>>(
        pph, ppl, DINO, pfwh, pfwl, DINO + D, nullptr, nullptr, ppp, nullptr, nullptr, D, DINO);
    // u + c0 (independent)
    u_kernel<<<M_ENC / 8, 256>>>(tokens, cls_w, cls_b, fus_w2, fus_b2, pu, pc0);

    for (int l = 0; l < L; l++) {
        gemm_bf16<true, false, false, true, false, false><<<dim3(3 * D / BN, M_ENC / BM), 256, GEMM_SMEM>>>(
            pxh, pxl, D, pqwh + (size_t)l * 3 * D * D, pqwl + (size_t)l * 3 * D * D, D,
            qkv_b + (size_t)l * 3 * D, nullptr, pqkv, nullptr, nullptr, 3 * D, D);
        attn_kernel<<<B * H, 256>>>(pqkv, pch, pcl);
        gemm_bf16<true, true, false, true, false, false><<<dim3(D / BN, M_ENC / BM), 256, GEMM_SMEM>>>(
            pch, pcl, D, powh + (size_t)l * D * D, powl + (size_t)l * D * D, D,
            out_b + (size_t)l * D, px, py, nullptr, nullptr, D, D);
        ln_kernel<<<M_ENC, 256>>>(py, ln1_s + (size_t)l * D, ln1_b + (size_t)l * D, px, pxh, pxl);
        gemm_bf16<true, false, true, false, true, false><<<dim3(DFF / BN, M_ENC / BM), 256, GEMM_SMEM>>>(
            pxh, pxl, D, pw1h + (size_t)l * DFF * D, pw1l + (size_t)l * DFF * D, D,
            b1 + (size_t)l * DFF, nullptr, nullptr, phh, phl, DFF, D);
        gemm_bf16<true, true, false, true, false, false><<<dim3(D / BN, M_ENC / BM), 256, GEMM_SMEM>>>(
            phh, phl, DFF, pw2h + (size_t)l * D * DFF, pw2l + (size_t)l * D * DFF, DFF,
            b2 + (size_t)l * D, px, py, nullptr, nullptr, D, DFF);
        ln_kernel<<<M_ENC, 256>>>(py, ln2_s + (size_t)l * D, ln2_b + (size_t)l * D, px, pxh, pxl);
    }

    // cproj = shift(x) @ wc^T + fus_b1  (shift folded into staging)
    gemm_bf16<true, false, false, true, false, true><<<dim3(D / BN, M_ENC / BM), 256, GEMM_SMEM>>>(
        pxh, pxl, D, pfwh + DINO, pfwl + DINO, DINO + D,
        fus_b1, nullptr, pcp, nullptr, nullptr, D, D);

    final_kernel<<<dim3(B, P / PT), 512, SMEM_FINAL>>>(ppp, pcp, pu, pc0, out);
}

// round 5
// speedup vs baseline: 2.2190x; 1.1306x over previous
#include <cuda_runtime.h>
#include <cuda_bf16.h>
#include <mma.h>
#include <stdint.h>

using namespace nvcuda;

// Model dims
constexpr int B = 32, T = 40, P = 256, V = 4096, D = 256, DINO = 384, H = 4, L = 2;
constexpr int HD = 64, DFF = 1024;
constexpr float EPS = 1e-5f;
constexpr int M_ENC = B * T;  // 1280

// ---------------- fp32 scratch ----------------
__device__ float g_x[M_ENC * D];
__device__ float g_y[M_ENC * D];
__device__ float g_qkv[M_ENC * 3 * D];
__device__ float g_pproj[B * P * D];
__device__ float g_cproj[M_ENC * D];
__device__ float g_u[M_ENC * D];
__device__ float g_c0[M_ENC];

// ---------------- bf16 hi/lo scratch ----------------
__device__ __nv_bfloat16 g_xh[M_ENC * D], g_xl[M_ENC * D];
__device__ __nv_bfloat16 g_ctxh[M_ENC * D], g_ctxl[M_ENC * D];
__device__ __nv_bfloat16 g_hh[M_ENC * DFF], g_hl2[M_ENC * DFF];
__device__ __nv_bfloat16 g_ph[B * P * DINO], g_pl[B * P * DINO];
__device__ __nv_bfloat16 g_qkvwh[L * 3 * D * D], g_qkvwl[L * 3 * D * D];
__device__ __nv_bfloat16 g_outwh[L * D * D], g_outwl[L * D * D];
__device__ __nv_bfloat16 g_w1h[L * DFF * D], g_w1l[L * DFF * D];
__device__ __nv_bfloat16 g_w2h[L * D * DFF], g_w2l[L * D * DFF];
__device__ __nv_bfloat16 g_fw1h[D * (DINO + D)], g_fw1l[D * (DINO + D)];

// ---------------- helpers ----------------
__device__ __forceinline__ uint32_t smem_u32(const void* p) {
    uint32_t a;
    asm("{ .reg .u64 t; cvta.to.shared.u64 t, %1; cvt.u32.u64 %0, t; }" : "=r"(a) : "l"(p));
    return a;
}
__device__ __forceinline__ void cpa16(uint32_t dst, const void* src, int sz) {
    asm volatile("cp.async.cg.shared.global [%0], [%1], 16, %2;" :: "r"(dst), "l"(src), "r"(sz));
}
__device__ __forceinline__ void cpa_commit() { asm volatile("cp.async.commit_group;"); }

__device__ __forceinline__ float gelu_f(float x) {
    float x2 = x * x;
    float targ = 0.7978845608f * x * fmaf(0.044715f, x2, 1.f);
    float th;
    asm("tanh.approx.f32 %0, %1;" : "=f"(th) : "f"(targ));
    return 0.5f * x * (1.f + th);
}

__device__ __forceinline__ void split4(float4 v, __nv_bfloat16* dh, __nv_bfloat16* dl, size_t off) {
    __nv_bfloat16 h0 = __float2bfloat16_rn(v.x), h1 = __float2bfloat16_rn(v.y);
    __nv_bfloat16 h2 = __float2bfloat16_rn(v.z), h3 = __float2bfloat16_rn(v.w);
    *reinterpret_cast<__nv_bfloat162*>(&dh[off]) = __nv_bfloat162(h0, h1);
    *reinterpret_cast<__nv_bfloat162*>(&dh[off + 2]) = __nv_bfloat162(h2, h3);
    __nv_bfloat16 l0 = __float2bfloat16_rn(v.x - __bfloat162float(h0));
    __nv_bfloat16 l1 = __float2bfloat16_rn(v.y - __bfloat162float(h1));
    __nv_bfloat16 l2 = __float2bfloat16_rn(v.z - __bfloat162float(h2));
    __nv_bfloat16 l3 = __float2bfloat16_rn(v.w - __bfloat162float(h3));
    *reinterpret_cast<__nv_bfloat162*>(&dl[off]) = __nv_bfloat162(l0, l1);
    *reinterpret_cast<__nv_bfloat162*>(&dl[off + 2]) = __nv_bfloat162(l2, l3);
}

// ---------------- prep A: encoder weights + embed ----------------
__global__ void __launch_bounds__(256) prep_enc_kernel(
    const float* __restrict__ qkv_w, const float* __restrict__ out_w,
    const float* __restrict__ w1, const float* __restrict__ w2,
    const int* __restrict__ tokens, const float* __restrict__ tok_emb,
    const float* __restrict__ pos_emb) {
    constexpr int S1 = L * 3 * D * D / 4;
    constexpr int S2 = L * D * D / 4;
    constexpr int S3 = L * DFF * D / 4;
    constexpr int S4 = L * D * DFF / 4;
    constexpr int S7 = M_ENC * D / 4;
    constexpr int TOT = S1 + S2 + S3 + S4 + S7;
    for (int i = blockIdx.x * blockDim.x + threadIdx.x; i < TOT; i += gridDim.x * blockDim.x) {
        int j = i;
        const float* src;
        __nv_bfloat16 *dh, *dl;
        if (j < S1) { src = qkv_w; dh = g_qkvwh; dl = g_qkvwl; }
        else if ((j -= S1) < S2) { src = out_w; dh = g_outwh; dl = g_outwl; }
        else if ((j -= S2) < S3) { src = w1; dh = g_w1h; dl = g_w1l; }
        else if ((j -= S3) < S4) { src = w2; dh = g_w2h; dl = g_w2l; }
        else {
            j -= S4;
            int bt = (j * 4) >> 8;
            int d0 = (j * 4) & 255;
            int t = bt % T;
            float4 te = *reinterpret_cast<const float4*>(&tok_emb[(size_t)tokens[bt] * D + d0]);
            float4 pe = *reinterpret_cast<const float4*>(&pos_emb[(size_t)t * D + d0]);
            float4 v = make_float4(te.x + pe.x, te.y + pe.y, te.z + pe.z, te.w + pe.w);
            *reinterpret_cast<float4*>(&g_x[(size_t)j * 4]) = v;
            split4(v, g_xh, g_xl, (size_t)j * 4);
            continue;
        }
        float4 v = *reinterpret_cast<const float4*>(&src[(size_t)j * 4]);
        split4(v, dh, dl, (size_t)j * 4);
    }
}

// ---------------- prep B: fusion weights + patches ----------------
__global__ void __launch_bounds__(256) prep_fus_kernel(
    const float* __restrict__ fus_w1, const float* __restrict__ patches) {
    constexpr int S5 = D * (DINO + D) / 4;
    constexpr int S6 = B * P * DINO / 4;
    constexpr int TOT = S5 + S6;
    for (int i = blockIdx.x * blockDim.x + threadIdx.x; i < TOT; i += gridDim.x * blockDim.x) {
        int j = i;
        const float* src;
        __nv_bfloat16 *dh, *dl;
        if (j < S5) { src = fus_w1; dh = g_fw1h; dl = g_fw1l; }
        else { j -= S5; src = patches; dh = g_ph; dl = g_pl; }
        float4 v = *reinterpret_cast<const float4*>(&src[(size_t)j * 4]);
        split4(v, dh, dl, (size_t)j * 4);
    }
}

// ======================= bf16 split GEMM, cp.async 3-stage =======================
constexpr int BM = 64, BN = 64, BK = 64;
constexpr int LDTE = 72;               // elements (144B rows, conflict-free ldmatrix)
constexpr int TILEB = 64 * LDTE * 2;   // 9216 bytes per tile-buffer
constexpr int NSTAGE = 3;
constexpr int GEMM_SMEM = NSTAGE * 4 * TILEB;   // 110592 B -> 2 CTAs/SM

template <bool BIAS, bool RES, bool RELU, bool EMIT32, bool EMITHL, bool SHIFT>
__global__ void __launch_bounds__(256, 2) gemm_bf16(
    const __nv_bfloat16* __restrict__ Ah, const __nv_bfloat16* __restrict__ Al, int lda,
    const __nv_bfloat16* __restrict__ Wh, const __nv_bfloat16* __restrict__ Wl, int ldw,
    const float* __restrict__ bias, const float* __restrict__ res,
    float* __restrict__ C32, __nv_bfloat16* __restrict__ Ch, __nv_bfloat16* __restrict__ Cl,
    int ldc, int K) {
    extern __shared__ char sm[];
    const int tid = threadIdx.x;
    const int n0 = blockIdx.x * BN;
    const int m0 = blockIdx.y * BM;
    const int nchunk = K / BK;
    const uint32_t sb0 = smem_u32(sm);

    auto stage = [&](int c) {
        const int buf = c % NSTAGE;
        const uint32_t sbase = sb0 + buf * 4 * TILEB;
        const int k0 = c * BK;
#pragma unroll
        for (int g = 0; g < 2; g++) {
            int gi = tid + g * 256;
            int row = gi >> 3, c16 = gi & 7;
            uint32_t soff = row * 144 + c16 * 16;
            int am = m0 + row;
            size_t aoff;
            int sz = 16;
            if (SHIFT) {
                int t = am % T;
                if (t == 0) { sz = 0; aoff = (size_t)am * lda + k0 + c16 * 8; }
                else aoff = (size_t)(am - 1) * lda + k0 + c16 * 8;
            } else {
                aoff = (size_t)am * lda + k0 + c16 * 8;
            }
            cpa16(sbase + 0 * TILEB + soff, Ah + aoff, sz);
            cpa16(sbase + 1 * TILEB + soff, Al + aoff, sz);
            size_t woff = (size_t)(n0 + row) * ldw + k0 + c16 * 8;
            cpa16(sbase + 2 * TILEB + soff, Wh + woff, 16);
            cpa16(sbase + 3 * TILEB + soff, Wl + woff, 16);
        }
        cpa_commit();
    };

    stage(0);
    if (nchunk > 1) stage(1);

    const int w = tid >> 5;
    const int wm = w >> 2;   // 0..1
    const int wn = w & 3;    // 0..3

    wmma::fragment<wmma::accumulator, 16, 16, 16, float> acc[2];
    wmma::fill_fragment(acc[0], 0.f);
    wmma::fill_fragment(acc[1], 0.f);

    for (int c = 0; c < nchunk; c++) {
        __syncthreads();   // all warps done with buf (c-1)%3 before overwrite
        if (c + 2 < nchunk) {
            stage(c + 2);
            asm volatile("cp.async.wait_group 2;");
        } else if (c + 1 < nchunk) {
            asm volatile("cp.async.wait_group 1;");
        } else {
            asm volatile("cp.async.wait_group 0;");
        }
        __syncthreads();
        char* bb = sm + (c % NSTAGE) * 4 * TILEB;
        const __nv_bfloat16* tAh = reinterpret_cast<const __nv_bfloat16*>(bb);
        const __nv_bfloat16* tAl = reinterpret_cast<const __nv_bfloat16*>(bb + TILEB);
        const __nv_bfloat16* tWh = reinterpret_cast<const __nv_bfloat16*>(bb + 2 * TILEB);
        const __nv_bfloat16* tWl = reinterpret_cast<const __nv_bfloat16*>(bb + 3 * TILEB);
#pragma unroll
        for (int ks = 0; ks < 4; ks++) {
            wmma::fragment<wmma::matrix_b, 16, 16, 16, __nv_bfloat16, wmma::col_major> bh, bl;
            wmma::load_matrix_sync(bh, &tWh[(wn * 16) * LDTE + ks * 16], LDTE);
            wmma::load_matrix_sync(bl, &tWl[(wn * 16) * LDTE + ks * 16], LDTE);
            wmma::fragment<wmma::matrix_a, 16, 16, 16, __nv_bfloat16, wmma::row_major> ah[2], al[2];
            wmma::load_matrix_sync(ah[0], &tAh[(wm * 32) * LDTE + ks * 16], LDTE);
            wmma::load_matrix_sync(ah[1], &tAh[(wm * 32 + 16) * LDTE + ks * 16], LDTE);
            wmma::load_matrix_sync(al[0], &tAl[(wm * 32) * LDTE + ks * 16], LDTE);
            wmma::load_matrix_sync(al[1], &tAl[(wm * 32 + 16) * LDTE + ks * 16], LDTE);
            // two interleaved dependency chains (acc[0], acc[1])
            wmma::mma_sync(acc[0], ah[0], bh, acc[0]);
            wmma::mma_sync(acc[1], ah[1], bh, acc[1]);
            wmma::mma_sync(acc[0], ah[0], bl, acc[0]);
            wmma::mma_sync(acc[1], ah[1], bl, acc[1]);
            wmma::mma_sync(acc[0], al[0], bh, acc[0]);
            wmma::mma_sync(acc[1], al[1], bh, acc[1]);
        }
    }
    __syncthreads();

    // epilogue via smem (aliases stage buffers), vectorized
    float* Cs = reinterpret_cast<float*>(sm);  // 64*72*4 = 18432 B
    wmma::store_matrix_sync(&Cs[(wm * 32) * LDTE + wn * 16], acc[0], LDTE, wmma::mem_row_major);
    wmma::store_matrix_sync(&Cs[(wm * 32 + 16) * LDTE + wn * 16], acc[1], LDTE, wmma::mem_row_major);
    __syncthreads();

#pragma unroll
    for (int i = tid * 4; i < BM * BN; i += 1024) {
        int r = i >> 6, cc = i & 63;
        int m = m0 + r, n = n0 + cc;
        float4 v = *reinterpret_cast<const float4*>(&Cs[r * LDTE + cc]);
        if (BIAS) {
            float4 bv = *reinterpret_cast<const float4*>(&bias[n]);
            v.x += bv.x; v.y += bv.y; v.z += bv.z; v.w += bv.w;
        }
        if (RES) {
            float4 rv = *reinterpret_cast<const float4*>(&res[(size_t)m * ldc + n]);
            v.x += rv.x; v.y += rv.y; v.z += rv.z; v.w += rv.w;
        }
        if (RELU) {
            v.x = fmaxf(v.x, 0.f); v.y = fmaxf(v.y, 0.f);
            v.z = fmaxf(v.z, 0.f); v.w = fmaxf(v.w, 0.f);
        }
        if (EMIT32) *reinterpret_cast<float4*>(&C32[(size_t)m * ldc + n]) = v;
        if (EMITHL) {
            __nv_bfloat16 h0 = __float2bfloat16_rn(v.x), h1 = __float2bfloat16_rn(v.y);
            __nv_bfloat16 h2 = __float2bfloat16_rn(v.z), h3 = __float2bfloat16_rn(v.w);
            __nv_bfloat162 hp0(h0, h1), hp1(h2, h3);
            *reinterpret_cast<__nv_bfloat162*>(&Ch[(size_t)m * ldc + n]) = hp0;
            *reinterpret_cast<__nv_bfloat162*>(&Ch[(size_t)m * ldc + n + 2]) = hp1;
            __nv_bfloat162 lp0(__float2bfloat16_rn(v.x - __bfloat162float(h0)),
                               __float2bfloat16_rn(v.y - __bfloat162float(h1)));
            __nv_bfloat162 lp1(__float2bfloat16_rn(v.z - __bfloat162float(h2)),
                               __float2bfloat16_rn(v.w - __bfloat162float(h3)));
            *reinterpret_cast<__nv_bfloat162*>(&Cl[(size_t)m * ldc + n]) = lp0;
            *reinterpret_cast<__nv_bfloat162*>(&Cl[(size_t)m * ldc + n + 2]) = lp1;
        }
    }
}

// ---------------- attention: one CTA per (b,h); emits ctx hi/lo ----------------
__global__ void __launch_bounds__(256) attn_kernel(const float* __restrict__ qkv,
                                                   __nv_bfloat16* __restrict__ ctxh,
                                                   __nv_bfloat16* __restrict__ ctxl) {
    int bh = blockIdx.x;
    int b = bh / H;
    int h = bh % H;
    __shared__ float Ks[T][HD + 1];
    __shared__ float Vs[T][HD + 1];
    __shared__ float Qs[8][HD];
    __shared__ float Ps[8][T];
    int tid = threadIdx.x;
    int w = tid >> 5, lane = tid & 31;
    for (int i = tid; i < T * HD; i += 256) {
        int t = i >> 6, d = i & 63;
        size_t base = ((size_t)(b * T + t)) * (3 * D) + h * HD + d;
        Ks[t][d] = qkv[base + D];
        Vs[t][d] = qkv[base + 2 * D];
    }
    __syncthreads();
    for (int r = w; r < T; r += 8) {
        size_t qb = ((size_t)(b * T + r)) * (3 * D) + h * HD;
        Qs[w][lane] = qkv[qb + lane];
        Qs[w][lane + 32] = qkv[qb + lane + 32];
        __syncwarp();
        int k0 = lane, k1 = lane + 32;
        float s0 = -1e30f, s1 = -1e30f;
        if (k0 <= r) {
            float a = 0.f;
#pragma unroll
            for (int d = 0; d < HD; d++) a += Qs[w][d] * Ks[k0][d];
            s0 = a * 0.125f;
        }
        if (k1 <= r && k1 < T) {
            float a = 0.f;
#pragma unroll
            for (int d = 0; d < HD; d++) a += Qs[w][d] * Ks[k1][d];
            s1 = a * 0.125f;
        }
        float m = fmaxf(s0, s1);
#pragma unroll
        for (int o = 16; o; o >>= 1) m = fmaxf(m, __shfl_xor_sync(0xffffffffu, m, o));
        float e0 = (k0 <= r) ? __expf(s0 - m) : 0.f;
        float e1 = (k1 <= r && k1 < T) ? __expf(s1 - m) : 0.f;
        float ssum = e0 + e1;
#pragma unroll
        for (int o = 16; o; o >>= 1) ssum += __shfl_xor_sync(0xffffffffu, ssum, o);
        float inv = 1.f / ssum;
        Ps[w][k0] = e0 * inv;
        if (k1 < T) Ps[w][k1] = e1 * inv;
        __syncwarp();
        float a0 = 0.f, a1 = 0.f;
        for (int k = 0; k <= r; k++) {
            float p = Ps[w][k];
            a0 += p * Vs[k][lane];
            a1 += p * Vs[k][lane + 32];
        }
        size_t ob = ((size_t)(b * T + r)) * D + h * HD;
        __nv_bfloat16 h0 = __float2bfloat16_rn(a0);
        __nv_bfloat16 h1 = __float2bfloat16_rn(a1);
        ctxh[ob + lane] = h0;
        ctxh[ob + lane + 32] = h1;
        ctxl[ob + lane] = __float2bfloat16_rn(a0 - __bfloat162float(h0));
        ctxl[ob + lane + 32] = __float2bfloat16_rn(a1 - __bfloat162float(h1));
        __syncwarp();
    }
}

// ---------------- layernorm over D=256 -> fp32 + hi/lo ----------------
__global__ void __launch_bounds__(256) ln_kernel(const float* __restrict__ in,
                                                 const float* __restrict__ sc,
                                                 const float* __restrict__ bi,
                                                 float* __restrict__ out32,
                                                 __nv_bfloat16* __restrict__ outh,
                                                 __nv_bfloat16* __restrict__ outl) {
    int row = blockIdx.x, tid = threadIdx.x;
    float v = in[(size_t)row * D + tid];
    float sum = v, sq = v * v;
#pragma unroll
    for (int o = 16; o; o >>= 1) {
        sum += __shfl_xor_sync(0xffffffffu, sum, o);
        sq += __shfl_xor_sync(0xffffffffu, sq, o);
    }
    __shared__ float r1[8], r2[8];
    int w = tid >> 5, lane = tid & 31;
    if (!lane) { r1[w] = sum; r2[w] = sq; }
    __syncthreads();
    if (w == 0) {
        float a = (lane < 8) ? r1[lane] : 0.f;
        float b2 = (lane < 8) ? r2[lane] : 0.f;
#pragma unroll
        for (int o = 4; o; o >>= 1) {
            a += __shfl_xor_sync(0xffffffffu, a, o);
            b2 += __shfl_xor_sync(0xffffffffu, b2, o);
        }
        if (!lane) { r1[0] = a; r2[0] = b2; }
    }
    __syncthreads();
    float mean = r1[0] * (1.f / 256.f);
    float var = r2[0] * (1.f / 256.f) - mean * mean;
    float o = (v - mean) * rsqrtf(var + EPS) * sc[tid] + bi[tid];
    size_t idx = (size_t)row * D + tid;
    out32[idx] = o;
    __nv_bfloat16 h = __float2bfloat16_rn(o);
    outh[idx] = h;
    outl[idx] = __float2bfloat16_rn(o - __bfloat162float(h));
}

// ---------------- u[bt,e] = sum_d cls_w[tok,d]*fus_w2[d,e]; c0 ----------------
__global__ void __launch_bounds__(256) u_kernel(const int* __restrict__ tokens,
                                                const float* __restrict__ cls_w,
                                                const float* __restrict__ cls_b,
                                                const float* __restrict__ fw2,
                                                const float* __restrict__ fb2,
                                                float* __restrict__ u,
                                                float* __restrict__ c0) {
    int bt0 = blockIdx.x * 8;
    int tid = threadIdx.x, w = tid >> 5, lane = tid & 31;
    __shared__ float ws[8][D];
    __shared__ int toksh[8];
    if (tid < 8) toksh[tid] = tokens[bt0 + tid];
    __syncthreads();
#pragma unroll
    for (int j = 0; j < 8; j++) ws[j][tid] = cls_w[(size_t)toksh[j] * D + tid];
    __syncthreads();
    {
        float s = 0.f;
        for (int d = lane; d < D; d += 32) s += fb2[d] * ws[w][d];
#pragma unroll
        for (int o = 16; o; o >>= 1) s += __shfl_xor_sync(0xffffffffu, s, o);
        if (!lane) c0[bt0 + w] = s + cls_b[toksh[w]];
    }
    float acc[8] = {};
    for (int d = 0; d < D; d++) {
        float f = fw2[(size_t)d * D + tid];
#pragma unroll
        for (int j = 0; j < 8; j++) acc[j] += ws[j][d] * f;
    }
#pragma unroll
    for (int j = 0; j < 8; j++) u[(size_t)(bt0 + j) * D + tid] = acc[j];
}

// ---------------- final fused gelu-dot + sigmoid ----------------
constexpr int PT = 64;
constexpr int PPAD = 65;
constexpr int SMEM_FINAL = (D * PPAD + T * D + T * D + T) * 4;

__global__ void __launch_bounds__(512) final_kernel(const float* __restrict__ pproj,
                                                    const float* __restrict__ cproj,
                                                    const float* __restrict__ u,
                                                    const float* __restrict__ c0,
                                                    float* __restrict__ out) {
    extern __shared__ float smf[];
    float* pps = smf;                 // [D][PPAD]
    float* cps = pps + D * PPAD;      // [T][D]
    float* us = cps + T * D;          // [T][D]
    float* c0s = us + T * D;          // [T]
    int b = blockIdx.x;
    int p0 = blockIdx.y * PT;
    int tid = threadIdx.x;
    for (int i = tid; i < PT * D; i += 512) {
        int p = i >> 8;
        int e = i & 255;
        pps[e * PPAD + p] = pproj[((size_t)(b * P + p0 + p)) * D + e];
    }
    for (int i = tid; i < T * D; i += 512) {
        cps[i] = cproj[(size_t)b * T * D + i];
        us[i] = u[(size_t)b * T * D + i];
    }
    if (tid < T) c0s[tid] = c0[b * T + tid];
    __syncthreads();

    int pl = tid & 63;
    int tg = tid >> 6;
    float acc[5] = {};
    for (int e = 0; e < D; e += 2) {
        float pe0 = pps[e * PPAD + pl];
        float pe1 = pps[(e + 1) * PPAD + pl];
#pragma unroll
        for (int i = 0; i < 5; i++) {
            int t = tg + 8 * i;
            float2 cp = *reinterpret_cast<const float2*>(&cps[t * D + e]);
            float2 uu = *reinterpret_cast<const float2*>(&us[t * D + e]);
            float x0 = pe0 + cp.x;
            float x1 = pe1 + cp.y;
            acc[i] += gelu_f(x0) * uu.x + gelu_f(x1) * uu.y;
        }
    }
    int p = p0 + pl;
#pragma unroll
    for (int i = 0; i < 5; i++) {
        int t = tg + 8 * i;
        float logit = acc[i] + c0s[t];
        out[((size_t)(b * P + p)) * T + t] = 1.f / (1.f + __expf(-logit));
    }
}

// ---------------- host ----------------
extern "C" void kernel_launch(void* const* d_in, const int* in_sizes, int n_in,
                              void* d_out, int out_size) {
    const float* patches = (const float*)d_in[0];
    const int* tokens = (const int*)d_in[1];
    const float* tok_emb = (const float*)d_in[2];
    const float* pos_emb = (const float*)d_in[3];
    const float* qkv_w = (const float*)d_in[4];
    const float* qkv_b = (const float*)d_in[5];
    const float* out_w = (const float*)d_in[6];
    const float* out_b = (const float*)d_in[7];
    const float* ln1_s = (const float*)d_in[8];
    const float* ln1_b = (const float*)d_in[9];
    const float* w1 = (const float*)d_in[10];
    const float* b1 = (const float*)d_in[11];
    const float* w2 = (const float*)d_in[12];
    const float* b2 = (const float*)d_in[13];
    const float* ln2_s = (const float*)d_in[14];
    const float* ln2_b = (const float*)d_in[15];
    const float* fus_w1 = (const float*)d_in[16];
    const float* fus_b1 = (const float*)d_in[17];
    const float* fus_w2 = (const float*)d_in[18];
    const float* fus_b2 = (const float*)d_in[19];
    const float* cls_w = (const float*)d_in[20];
    const float* cls_b = (const float*)d_in[21];
    float* out = (float*)d_out;

    float *px, *py, *pqkv, *ppp, *pcp, *pu, *pc0;
    cudaGetSymbolAddress((void**)&px, g_x);
    cudaGetSymbolAddress((void**)&py, g_y);
    cudaGetSymbolAddress((void**)&pqkv, g_qkv);
    cudaGetSymbolAddress((void**)&ppp, g_pproj);
    cudaGetSymbolAddress((void**)&pcp, g_cproj);
    cudaGetSymbolAddress((void**)&pu, g_u);
    cudaGetSymbolAddress((void**)&pc0, g_c0);

    __nv_bfloat16 *pxh, *pxl, *pch, *pcl, *phh, *phl, *pph, *ppl;
    __nv_bfloat16 *pqwh, *pqwl, *powh, *powl, *pw1h, *pw1l, *pw2h, *pw2l, *pfwh, *pfwl;
    cudaGetSymbolAddress((void**)&pxh, g_xh);
    cudaGetSymbolAddress((void**)&pxl, g_xl);
    cudaGetSymbolAddress((void**)&pch, g_ctxh);
    cudaGetSymbolAddress((void**)&pcl, g_ctxl);
    cudaGetSymbolAddress((void**)&phh, g_hh);
    cudaGetSymbolAddress((void**)&phl, g_hl2);
    cudaGetSymbolAddress((void**)&pph, g_ph);
    cudaGetSymbolAddress((void**)&ppl, g_pl);
    cudaGetSymbolAddress((void**)&pqwh, g_qkvwh);
    cudaGetSymbolAddress((void**)&pqwl, g_qkvwl);
    cudaGetSymbolAddress((void**)&powh, g_outwh);
    cudaGetSymbolAddress((void**)&powl, g_outwl);
    cudaGetSymbolAddress((void**)&pw1h, g_w1h);
    cudaGetSymbolAddress((void**)&pw1l, g_w1l);
    cudaGetSymbolAddress((void**)&pw2h, g_w2h);
    cudaGetSymbolAddress((void**)&pw2l, g_w2l);
    cudaGetSymbolAddress((void**)&pfwh, g_fw1h);
    cudaGetSymbolAddress((void**)&pfwl, g_fw1l);

    cudaFuncSetAttribute(final_kernel, cudaFuncAttributeMaxDynamicSharedMemorySize, SMEM_FINAL);
    cudaFuncSetAttribute(gemm_bf16<true, false, false, true, false, false>, cudaFuncAttributeMaxDynamicSharedMemorySize, GEMM_SMEM);
    cudaFuncSetAttribute(gemm_bf16<true, true, false, true, false, false>, cudaFuncAttributeMaxDynamicSharedMemorySize, GEMM_SMEM);
    cudaFuncSetAttribute(gemm_bf16<true, false, true, false, true, false>, cudaFuncAttributeMaxDynamicSharedMemorySize, GEMM_SMEM);
    cudaFuncSetAttribute(gemm_bf16<false, false, false, true, false, false>, cudaFuncAttributeMaxDynamicSharedMemorySize, GEMM_SMEM);
    cudaFuncSetAttribute(gemm_bf16<true, false, false, true, false, true>, cudaFuncAttributeMaxDynamicSharedMemorySize, GEMM_SMEM);

    // streams/events for graph-captured fork (host objects, created once)
    static cudaStream_t s1 = nullptr, s2 = nullptr;
    static cudaEvent_t ev0 = nullptr, ev1 = nullptr, ev2 = nullptr;
    if (!s1) {
        cudaStreamCreateWithFlags(&s1, cudaStreamNonBlocking);
        cudaStreamCreateWithFlags(&s2, cudaStreamNonBlocking);
        cudaEventCreateWithFlags(&ev0, cudaEventDisableTiming);
        cudaEventCreateWithFlags(&ev1, cudaEventDisableTiming);
        cudaEventCreateWithFlags(&ev2, cudaEventDisableTiming);
    }

    // fork
    cudaEventRecord(ev0, 0);
    cudaStreamWaitEvent(s1, ev0, 0);
    cudaStreamWaitEvent(s2, ev0, 0);

    // branch s1: fusion prep + pproj
    prep_fus_kernel<<<1024, 256, 0, s1>>>(fus_w1, patches);
    gemm_bf16<false, false, false, true, false, false><<<dim3(D / BN, B * P / BM), 256, GEMM_SMEM, s1>>>(
        pph, ppl, DINO, pfwh, pfwl, DINO + D, nullptr, nullptr, ppp, nullptr, nullptr, D, DINO);
    cudaEventRecord(ev1, s1);

    // branch s2: u + c0
    u_kernel<<<M_ENC / 8, 256, 0, s2>>>(tokens, cls_w, cls_b, fus_w2, fus_b2, pu, pc0);
    cudaEventRecord(ev2, s2);

    // main branch: encoder
    prep_enc_kernel<<<1024, 256>>>(qkv_w, out_w, w1, w2, tokens, tok_emb, pos_emb);

    for (int l = 0; l < L; l++) {
        gemm_bf16<true, false, false, true, false, false><<<dim3(3 * D / BN, M_ENC / BM), 256, GEMM_SMEM>>>(
            pxh, pxl, D, pqwh + (size_t)l * 3 * D * D, pqwl + (size_t)l * 3 * D * D, D,
            qkv_b + (size_t)l * 3 * D, nullptr, pqkv, nullptr, nullptr, 3 * D, D);
        attn_kernel<<<B * H, 256>>>(pqkv, pch, pcl);
        gemm_bf16<true, true, false, true, false, false><<<dim3(D / BN, M_ENC / BM), 256, GEMM_SMEM>>>(
            pch, pcl, D, powh + (size_t)l * D * D, powl + (size_t)l * D * D, D,
            out_b + (size_t)l * D, px, py, nullptr, nullptr, D, D);
        ln_kernel<<<M_ENC, 256>>>(py, ln1_s + (size_t)l * D, ln1_b + (size_t)l * D, px, pxh, pxl);
        gemm_bf16<true, false, true, false, true, false><<<dim3(DFF / BN, M_ENC / BM), 256, GEMM_SMEM>>>(
            pxh, pxl, D, pw1h + (size_t)l * DFF * D, pw1l + (size_t)l * DFF * D, D,
            b1 + (size_t)l * DFF, nullptr, nullptr, phh, phl, DFF, D);
        gemm_bf16<true, true, false, true, false, false><<<dim3(D / BN, M_ENC / BM), 256, GEMM_SMEM>>>(
            phh, phl, DFF, pw2h + (size_t)l * D * DFF, pw2l + (size_t)l * D * DFF, DFF,
            b2 + (size_t)l * D, px, py, nullptr, nullptr, D, DFF);
        ln_kernel<<<M_ENC, 256>>>(py, ln2_s + (size_t)l * D, ln2_b + (size_t)l * D, px, pxh, pxl);
    }

    // join: cproj needs fus_w1 split (s1 branch)
    cudaStreamWaitEvent(0, ev1, 0);
    gemm_bf16<true, false, false, true, false, true><<<dim3(D / BN, M_ENC / BM), 256, GEMM_SMEM>>>(
        pxh, pxl, D, pfwh + DINO, pfwl + DINO, DINO + D,
        fus_b1, nullptr, pcp, nullptr, nullptr, D, D);

    cudaStreamWaitEvent(0, ev2, 0);
    final_kernel<<<dim3(B, P / PT), 512, SMEM_FINAL>>>(ppp, pcp, pu, pc0, out);
}

// round 6
// speedup vs baseline: 2.3014x; 1.0371x over previous
#include <cuda_runtime.h>
#include <cuda_bf16.h>
#include <mma.h>
#include <stdint.h>

using namespace nvcuda;

// Model dims
constexpr int B = 32, T = 40, P = 256, V = 4096, D = 256, DINO = 384, H = 4, L = 2;
constexpr int HD = 64, DFF = 1024;
constexpr float EPS = 1e-5f;
constexpr int M_ENC = B * T;  // 1280

// ---------------- fp32 scratch ----------------
__device__ float g_x[M_ENC * D];
__device__ float g_y[M_ENC * D];
__device__ float g_qkv[M_ENC * 3 * D];
__device__ float g_pproj[B * P * D];
__device__ float g_cproj[M_ENC * D];
__device__ float g_u[M_ENC * D];
__device__ float g_c0[M_ENC];

// ---------------- bf16 hi/lo scratch ----------------
__device__ __nv_bfloat16 g_xh[M_ENC * D], g_xl[M_ENC * D];
__device__ __nv_bfloat16 g_ctxh[M_ENC * D], g_ctxl[M_ENC * D];
__device__ __nv_bfloat16 g_hh[M_ENC * DFF], g_hl2[M_ENC * DFF];
__device__ __nv_bfloat16 g_ph[B * P * DINO], g_pl[B * P * DINO];
__device__ __nv_bfloat16 g_qkvwh[L * 3 * D * D], g_qkvwl[L * 3 * D * D];
__device__ __nv_bfloat16 g_outwh[L * D * D], g_outwl[L * D * D];
__device__ __nv_bfloat16 g_w1h[L * DFF * D], g_w1l[L * DFF * D];
__device__ __nv_bfloat16 g_w2h[L * D * DFF], g_w2l[L * D * DFF];
__device__ __nv_bfloat16 g_fw1h[D * (DINO + D)], g_fw1l[D * (DINO + D)];

// ---------------- helpers ----------------
__device__ __forceinline__ uint32_t smem_u32(const void* p) {
    uint32_t a;
    asm("{ .reg .u64 t; cvta.to.shared.u64 t, %1; cvt.u32.u64 %0, t; }" : "=r"(a) : "l"(p));
    return a;
}
__device__ __forceinline__ void cpa16(uint32_t dst, const void* src, int sz) {
    asm volatile("cp.async.cg.shared.global [%0], [%1], 16, %2;" :: "r"(dst), "l"(src), "r"(sz));
}
__device__ __forceinline__ void cpa_commit() { asm volatile("cp.async.commit_group;"); }

__device__ __forceinline__ void split4(float4 v, __nv_bfloat16* dh, __nv_bfloat16* dl, size_t off) {
    __nv_bfloat16 h0 = __float2bfloat16_rn(v.x), h1 = __float2bfloat16_rn(v.y);
    __nv_bfloat16 h2 = __float2bfloat16_rn(v.z), h3 = __float2bfloat16_rn(v.w);
    *reinterpret_cast<__nv_bfloat162*>(&dh[off]) = __nv_bfloat162(h0, h1);
    *reinterpret_cast<__nv_bfloat162*>(&dh[off + 2]) = __nv_bfloat162(h2, h3);
    __nv_bfloat16 l0 = __float2bfloat16_rn(v.x - __bfloat162float(h0));
    __nv_bfloat16 l1 = __float2bfloat16_rn(v.y - __bfloat162float(h1));
    __nv_bfloat16 l2 = __float2bfloat16_rn(v.z - __bfloat162float(h2));
    __nv_bfloat16 l3 = __float2bfloat16_rn(v.w - __bfloat162float(h3));
    *reinterpret_cast<__nv_bfloat162*>(&dl[off]) = __nv_bfloat162(l0, l1);
    *reinterpret_cast<__nv_bfloat162*>(&dl[off + 2]) = __nv_bfloat162(l2, l3);
}

// ---------------- prep A: encoder weights + embed ----------------
__global__ void __launch_bounds__(256) prep_enc_kernel(
    const float* __restrict__ qkv_w, const float* __restrict__ out_w,
    const float* __restrict__ w1, const float* __restrict__ w2,
    const int* __restrict__ tokens, const float* __restrict__ tok_emb,
    const float* __restrict__ pos_emb) {
    constexpr int S1 = L * 3 * D * D / 4;
    constexpr int S2 = L * D * D / 4;
    constexpr int S3 = L * DFF * D / 4;
    constexpr int S4 = L * D * DFF / 4;
    constexpr int S7 = M_ENC * D / 4;
    constexpr int TOT = S1 + S2 + S3 + S4 + S7;
    for (int i = blockIdx.x * blockDim.x + threadIdx.x; i < TOT; i += gridDim.x * blockDim.x) {
        int j = i;
        const float* src;
        __nv_bfloat16 *dh, *dl;
        if (j < S1) { src = qkv_w; dh = g_qkvwh; dl = g_qkvwl; }
        else if ((j -= S1) < S2) { src = out_w; dh = g_outwh; dl = g_outwl; }
        else if ((j -= S2) < S3) { src = w1; dh = g_w1h; dl = g_w1l; }
        else if ((j -= S3) < S4) { src = w2; dh = g_w2h; dl = g_w2l; }
        else {
            j -= S4;
            int bt = (j * 4) >> 8;
            int d0 = (j * 4) & 255;
            int t = bt % T;
            float4 te = *reinterpret_cast<const float4*>(&tok_emb[(size_t)tokens[bt] * D + d0]);
            float4 pe = *reinterpret_cast<const float4*>(&pos_emb[(size_t)t * D + d0]);
            float4 v = make_float4(te.x + pe.x, te.y + pe.y, te.z + pe.z, te.w + pe.w);
            *reinterpret_cast<float4*>(&g_x[(size_t)j * 4]) = v;
            split4(v, g_xh, g_xl, (size_t)j * 4);
            continue;
        }
        float4 v = *reinterpret_cast<const float4*>(&src[(size_t)j * 4]);
        split4(v, dh, dl, (size_t)j * 4);
    }
}

// ---------------- prep B: fusion weights + patches ----------------
__global__ void __launch_bounds__(256) prep_fus_kernel(
    const float* __restrict__ fus_w1, const float* __restrict__ patches) {
    constexpr int S5 = D * (DINO + D) / 4;
    constexpr int S6 = B * P * DINO / 4;
    constexpr int TOT = S5 + S6;
    for (int i = blockIdx.x * blockDim.x + threadIdx.x; i < TOT; i += gridDim.x * blockDim.x) {
        int j = i;
        const float* src;
        __nv_bfloat16 *dh, *dl;
        if (j < S5) { src = fus_w1; dh = g_fw1h; dl = g_fw1l; }
        else { j -= S5; src = patches; dh = g_ph; dl = g_pl; }
        float4 v = *reinterpret_cast<const float4*>(&src[(size_t)j * 4]);
        split4(v, dh, dl, (size_t)j * 4);
    }
}

// ======================= bf16 split GEMM, cp.async 2-stage, 3 CTA/SM =======================
constexpr int BM = 64, BN = 64, BK = 64;
constexpr int LDTE = 72;               // elements (144B rows, conflict-free ldmatrix)
constexpr int TILEB = 64 * LDTE * 2;   // 9216 bytes per tile-buffer
constexpr int NSTAGE = 2;
constexpr int GEMM_SMEM = NSTAGE * 4 * TILEB;   // 73728 B -> 3 CTAs/SM

template <bool BIAS, bool RES, bool RELU, bool EMIT32, bool EMITHL, bool SHIFT>
__global__ void __launch_bounds__(256, 3) gemm_bf16(
    const __nv_bfloat16* __restrict__ Ah, const __nv_bfloat16* __restrict__ Al, int lda,
    const __nv_bfloat16* __restrict__ Wh, const __nv_bfloat16* __restrict__ Wl, int ldw,
    const float* __restrict__ bias, const float* __restrict__ res,
    float* __restrict__ C32, __nv_bfloat16* __restrict__ Ch, __nv_bfloat16* __restrict__ Cl,
    int ldc, int K) {
    extern __shared__ char sm[];
    const int tid = threadIdx.x;
    const int n0 = blockIdx.x * BN;
    const int m0 = blockIdx.y * BM;
    const int nchunk = K / BK;
    const uint32_t sb0 = smem_u32(sm);

    auto stage = [&](int c) {
        const int buf = c & 1;
        const uint32_t sbase = sb0 + buf * 4 * TILEB;
        const int k0 = c * BK;
#pragma unroll
        for (int g = 0; g < 2; g++) {
            int gi = tid + g * 256;
            int row = gi >> 3, c16 = gi & 7;
            uint32_t soff = row * 144 + c16 * 16;
            int am = m0 + row;
            size_t aoff;
            int sz = 16;
            if (SHIFT) {
                int t = am % T;
                if (t == 0) { sz = 0; aoff = (size_t)am * lda + k0 + c16 * 8; }
                else aoff = (size_t)(am - 1) * lda + k0 + c16 * 8;
            } else {
                aoff = (size_t)am * lda + k0 + c16 * 8;
            }
            cpa16(sbase + 0 * TILEB + soff, Ah + aoff, sz);
            cpa16(sbase + 1 * TILEB + soff, Al + aoff, sz);
            size_t woff = (size_t)(n0 + row) * ldw + k0 + c16 * 8;
            cpa16(sbase + 2 * TILEB + soff, Wh + woff, 16);
            cpa16(sbase + 3 * TILEB + soff, Wl + woff, 16);
        }
        cpa_commit();
    };

    stage(0);
    if (nchunk > 1) stage(1);

    const int w = tid >> 5;
    const int wm = w >> 2;   // 0..1
    const int wn = w & 3;    // 0..3

    wmma::fragment<wmma::accumulator, 16, 16, 16, float> acc[2];
    wmma::fill_fragment(acc[0], 0.f);
    wmma::fill_fragment(acc[1], 0.f);

    for (int c = 0; c < nchunk; c++) {
        if (c + 1 < nchunk) {
            asm volatile("cp.async.wait_group 1;");
        } else {
            asm volatile("cp.async.wait_group 0;");
        }
        __syncthreads();
        char* bb = sm + (c & 1) * 4 * TILEB;
        const __nv_bfloat16* tAh = reinterpret_cast<const __nv_bfloat16*>(bb);
        const __nv_bfloat16* tAl = reinterpret_cast<const __nv_bfloat16*>(bb + TILEB);
        const __nv_bfloat16* tWh = reinterpret_cast<const __nv_bfloat16*>(bb + 2 * TILEB);
        const __nv_bfloat16* tWl = reinterpret_cast<const __nv_bfloat16*>(bb + 3 * TILEB);
#pragma unroll
        for (int ks = 0; ks < 4; ks++) {
            wmma::fragment<wmma::matrix_b, 16, 16, 16, __nv_bfloat16, wmma::col_major> bh, bl;
            wmma::load_matrix_sync(bh, &tWh[(wn * 16) * LDTE + ks * 16], LDTE);
            wmma::load_matrix_sync(bl, &tWl[(wn * 16) * LDTE + ks * 16], LDTE);
            wmma::fragment<wmma::matrix_a, 16, 16, 16, __nv_bfloat16, wmma::row_major> ah[2], al[2];
            wmma::load_matrix_sync(ah[0], &tAh[(wm * 32) * LDTE + ks * 16], LDTE);
            wmma::load_matrix_sync(ah[1], &tAh[(wm * 32 + 16) * LDTE + ks * 16], LDTE);
            wmma::load_matrix_sync(al[0], &tAl[(wm * 32) * LDTE + ks * 16], LDTE);
            wmma::load_matrix_sync(al[1], &tAl[(wm * 32 + 16) * LDTE + ks * 16], LDTE);
            wmma::mma_sync(acc[0], ah[0], bh, acc[0]);
            wmma::mma_sync(acc[1], ah[1], bh, acc[1]);
            wmma::mma_sync(acc[0], ah[0], bl, acc[0]);
            wmma::mma_sync(acc[1], ah[1], bl, acc[1]);
            wmma::mma_sync(acc[0], al[0], bh, acc[0]);
            wmma::mma_sync(acc[1], al[1], bh, acc[1]);
        }
        __syncthreads();
        if (c + 2 < nchunk) stage(c + 2);
    }

    // epilogue via smem (aliases stage buffers), vectorized
    float* Cs = reinterpret_cast<float*>(sm);  // 64*72*4 = 18432 B
    wmma::store_matrix_sync(&Cs[(wm * 32) * LDTE + wn * 16], acc[0], LDTE, wmma::mem_row_major);
    wmma::store_matrix_sync(&Cs[(wm * 32 + 16) * LDTE + wn * 16], acc[1], LDTE, wmma::mem_row_major);
    __syncthreads();

#pragma unroll
    for (int i = tid * 4; i < BM * BN; i += 1024) {
        int r = i >> 6, cc = i & 63;
        int m = m0 + r, n = n0 + cc;
        float4 v = *reinterpret_cast<const float4*>(&Cs[r * LDTE + cc]);
        if (BIAS) {
            float4 bv = *reinterpret_cast<const float4*>(&bias[n]);
            v.x += bv.x; v.y += bv.y; v.z += bv.z; v.w += bv.w;
        }
        if (RES) {
            float4 rv = *reinterpret_cast<const float4*>(&res[(size_t)m * ldc + n]);
            v.x += rv.x; v.y += rv.y; v.z += rv.z; v.w += rv.w;
        }
        if (RELU) {
            v.x = fmaxf(v.x, 0.f); v.y = fmaxf(v.y, 0.f);
            v.z = fmaxf(v.z, 0.f); v.w = fmaxf(v.w, 0.f);
        }
        if (EMIT32) *reinterpret_cast<float4*>(&C32[(size_t)m * ldc + n]) = v;
        if (EMITHL) {
            __nv_bfloat16 h0 = __float2bfloat16_rn(v.x), h1 = __float2bfloat16_rn(v.y);
            __nv_bfloat16 h2 = __float2bfloat16_rn(v.z), h3 = __float2bfloat16_rn(v.w);
            __nv_bfloat162 hp0(h0, h1), hp1(h2, h3);
            *reinterpret_cast<__nv_bfloat162*>(&Ch[(size_t)m * ldc + n]) = hp0;
            *reinterpret_cast<__nv_bfloat162*>(&Ch[(size_t)m * ldc + n + 2]) = hp1;
            __nv_bfloat162 lp0(__float2bfloat16_rn(v.x - __bfloat162float(h0)),
                               __float2bfloat16_rn(v.y - __bfloat162float(h1)));
            __nv_bfloat162 lp1(__float2bfloat16_rn(v.z - __bfloat162float(h2)),
                               __float2bfloat16_rn(v.w - __bfloat162float(h3)));
            *reinterpret_cast<__nv_bfloat162*>(&Cl[(size_t)m * ldc + n]) = lp0;
            *reinterpret_cast<__nv_bfloat162*>(&Cl[(size_t)m * ldc + n + 2]) = lp1;
        }
    }
}

// ---------------- attention: one CTA per (b,h); emits ctx hi/lo ----------------
__global__ void __launch_bounds__(256) attn_kernel(const float* __restrict__ qkv,
                                                   __nv_bfloat16* __restrict__ ctxh,
                                                   __nv_bfloat16* __restrict__ ctxl) {
    int bh = blockIdx.x;
    int b = bh / H;
    int h = bh % H;
    __shared__ float Ks[T][HD + 1];
    __shared__ float Vs[T][HD + 1];
    __shared__ float Qs[8][HD];
    __shared__ float Ps[8][T];
    int tid = threadIdx.x;
    int w = tid >> 5, lane = tid & 31;
    for (int i = tid; i < T * HD; i += 256) {
        int t = i >> 6, d = i & 63;
        size_t base = ((size_t)(b * T + t)) * (3 * D) + h * HD + d;
        Ks[t][d] = qkv[base + D];
        Vs[t][d] = qkv[base + 2 * D];
    }
    __syncthreads();
    for (int r = w; r < T; r += 8) {
        size_t qb = ((size_t)(b * T + r)) * (3 * D) + h * HD;
        Qs[w][lane] = qkv[qb + lane];
        Qs[w][lane + 32] = qkv[qb + lane + 32];
        __syncwarp();
        int k0 = lane, k1 = lane + 32;
        float s0 = -1e30f, s1 = -1e30f;
        if (k0 <= r) {
            float a = 0.f;
#pragma unroll
            for (int d = 0; d < HD; d++) a += Qs[w][d] * Ks[k0][d];
            s0 = a * 0.125f;
        }
        if (k1 <= r && k1 < T) {
            float a = 0.f;
#pragma unroll
            for (int d = 0; d < HD; d++) a += Qs[w][d] * Ks[k1][d];
            s1 = a * 0.125f;
        }
        float m = fmaxf(s0, s1);
#pragma unroll
        for (int o = 16; o; o >>= 1) m = fmaxf(m, __shfl_xor_sync(0xffffffffu, m, o));
        float e0 = (k0 <= r) ? __expf(s0 - m) : 0.f;
        float e1 = (k1 <= r && k1 < T) ? __expf(s1 - m) : 0.f;
        float ssum = e0 + e1;
#pragma unroll
        for (int o = 16; o; o >>= 1) ssum += __shfl_xor_sync(0xffffffffu, ssum, o);
        float inv = 1.f / ssum;
        Ps[w][k0] = e0 * inv;
        if (k1 < T) Ps[w][k1] = e1 * inv;
        __syncwarp();
        float a0 = 0.f, a1 = 0.f;
        for (int k = 0; k <= r; k++) {
            float p = Ps[w][k];
            a0 += p * Vs[k][lane];
            a1 += p * Vs[k][lane + 32];
        }
        size_t ob = ((size_t)(b * T + r)) * D + h * HD;
        __nv_bfloat16 h0 = __float2bfloat16_rn(a0);
        __nv_bfloat16 h1 = __float2bfloat16_rn(a1);
        ctxh[ob + lane] = h0;
        ctxh[ob + lane + 32] = h1;
        ctxl[ob + lane] = __float2bfloat16_rn(a0 - __bfloat162float(h0));
        ctxl[ob + lane + 32] = __float2bfloat16_rn(a1 - __bfloat162float(h1));
        __syncwarp();
    }
}

// ---------------- layernorm over D=256 -> fp32 + hi/lo ----------------
__global__ void __launch_bounds__(256) ln_kernel(const float* __restrict__ in,
                                                 const float* __restrict__ sc,
                                                 const float* __restrict__ bi,
                                                 float* __restrict__ out32,
                                                 __nv_bfloat16* __restrict__ outh,
                                                 __nv_bfloat16* __restrict__ outl) {
    int row = blockIdx.x, tid = threadIdx.x;
    float v = in[(size_t)row * D + tid];
    float sum = v, sq = v * v;
#pragma unroll
    for (int o = 16; o; o >>= 1) {
        sum += __shfl_xor_sync(0xffffffffu, sum, o);
        sq += __shfl_xor_sync(0xffffffffu, sq, o);
    }
    __shared__ float r1[8], r2[8];
    int w = tid >> 5, lane = tid & 31;
    if (!lane) { r1[w] = sum; r2[w] = sq; }
    __syncthreads();
    if (w == 0) {
        float a = (lane < 8) ? r1[lane] : 0.f;
        float b2 = (lane < 8) ? r2[lane] : 0.f;
#pragma unroll
        for (int o = 4; o; o >>= 1) {
            a += __shfl_xor_sync(0xffffffffu, a, o);
            b2 += __shfl_xor_sync(0xffffffffu, b2, o);
        }
        if (!lane) { r1[0] = a; r2[0] = b2; }
    }
    __syncthreads();
    float mean = r1[0] * (1.f / 256.f);
    float var = r2[0] * (1.f / 256.f) - mean * mean;
    float o = (v - mean) * rsqrtf(var + EPS) * sc[tid] + bi[tid];
    size_t idx = (size_t)row * D + tid;
    out32[idx] = o;
    __nv_bfloat16 h = __float2bfloat16_rn(o);
    outh[idx] = h;
    outl[idx] = __float2bfloat16_rn(o - __bfloat162float(h));
}

// ---------------- u (scaled by 0.5) + c0 ----------------
__global__ void __launch_bounds__(256) u_kernel(const int* __restrict__ tokens,
                                                const float* __restrict__ cls_w,
                                                const float* __restrict__ cls_b,
                                                const float* __restrict__ fw2,
                                                const float* __restrict__ fb2,
                                                float* __restrict__ u,
                                                float* __restrict__ c0) {
    int bt0 = blockIdx.x * 8;
    int tid = threadIdx.x, w = tid >> 5, lane = tid & 31;
    __shared__ float ws[8][D];
    __shared__ int toksh[8];
    if (tid < 8) toksh[tid] = tokens[bt0 + tid];
    __syncthreads();
#pragma unroll
    for (int j = 0; j < 8; j++) ws[j][tid] = cls_w[(size_t)toksh[j] * D + tid];
    __syncthreads();
    {
        float s = 0.f;
        for (int d = lane; d < D; d += 32) s += fb2[d] * ws[w][d];
#pragma unroll
        for (int o = 16; o; o >>= 1) s += __shfl_xor_sync(0xffffffffu, s, o);
        if (!lane) c0[bt0 + w] = s + cls_b[toksh[w]];
    }
    float acc[8] = {};
    for (int d = 0; d < D; d++) {
        float f = fw2[(size_t)d * D + tid];
#pragma unroll
        for (int j = 0; j < 8; j++) acc[j] += ws[j][d] * f;
    }
#pragma unroll
    for (int j = 0; j < 8; j++) u[(size_t)(bt0 + j) * D + tid] = 0.5f * acc[j];
}

// ---------------- final fused gelu-dot + sigmoid (t-split, 2 CTA/SM) ----------------
constexpr int PT = 64;
constexpr int PPAD = 65;
constexpr int TT = 20;     // t per CTA (T/2)
constexpr int SMEM_FINAL = (D * PPAD + TT * D + TT * D + TT) * 4;  // 107,600 B

__global__ void __launch_bounds__(512, 2) final_kernel(const float* __restrict__ pproj,
                                                       const float* __restrict__ cproj,
                                                       const float* __restrict__ u,
                                                       const float* __restrict__ c0,
                                                       float* __restrict__ out) {
    extern __shared__ float smf[];
    float* pps = smf;                  // [D][PPAD]
    float* cps = pps + D * PPAD;       // [TT][D]
    float* us = cps + TT * D;          // [TT][D]  (holds 0.5*u)
    float* c0s = us + TT * D;          // [TT]
    int b = blockIdx.x;
    int p0 = blockIdx.y * PT;
    int tb0 = blockIdx.z * TT;
    int tid = threadIdx.x;
    for (int i = tid; i < PT * D; i += 512) {
        int p = i >> 8;
        int e = i & 255;
        pps[e * PPAD + p] = pproj[((size_t)(b * P + p0 + p)) * D + e];
    }
    for (int i = tid; i < TT * D; i += 512) {
        cps[i] = cproj[(size_t)(b * T + tb0) * D + i];
        us[i] = u[(size_t)(b * T + tb0) * D + i];
    }
    if (tid < TT) c0s[tid] = c0[b * T + tb0 + tid];
    __syncthreads();

    int pl = tid & 63;
    int tg = tid >> 6;                  // 0..7 (warp-uniform)
    const int nt = (tg < TT - 16) ? 3 : 2;  // t = tg, tg+8, (tg+16 if < TT)
    float acc[3] = {};
    for (int e = 0; e < D; e += 2) {
        float pe0 = pps[e * PPAD + pl];
        float pe1 = pps[(e + 1) * PPAD + pl];
#pragma unroll 3
        for (int i = 0; i < 3; i++) {
            if (i < nt) {
                int t = tg + 8 * i;
                float2 cp = *reinterpret_cast<const float2*>(&cps[t * D + e]);
                float2 uu = *reinterpret_cast<const float2*>(&us[t * D + e]);
                float x0 = pe0 + cp.x;
                float x1 = pe1 + cp.y;
                float t10 = fmaf(0.035677408f, x0 * x0, 0.7978845608f);
                float t11 = fmaf(0.035677408f, x1 * x1, 0.7978845608f);
                float th0, th1;
                asm("tanh.approx.f32 %0, %1;" : "=f"(th0) : "f"(x0 * t10));
                asm("tanh.approx.f32 %0, %1;" : "=f"(th1) : "f"(x1 * t11));
                float w0 = x0 * uu.x;   // uu = 0.5*u
                float w1 = x1 * uu.y;
                acc[i] = fmaf(w0, th0, acc[i] + w0);
                acc[i] = fmaf(w1, th1, acc[i] + w1);
            }
        }
    }
    int p = p0 + pl;
#pragma unroll 3
    for (int i = 0; i < 3; i++) {
        if (i < nt) {
            int t = tg + 8 * i;
            float logit = acc[i] + c0s[t];
            out[((size_t)(b * P + p)) * T + tb0 + t] = 1.f / (1.f + __expf(-logit));
        }
    }
}

// ---------------- host ----------------
extern "C" void kernel_launch(void* const* d_in, const int* in_sizes, int n_in,
                              void* d_out, int out_size) {
    const float* patches = (const float*)d_in[0];
    const int* tokens = (const int*)d_in[1];
    const float* tok_emb = (const float*)d_in[2];
    const float* pos_emb = (const float*)d_in[3];
    const float* qkv_w = (const float*)d_in[4];
    const float* qkv_b = (const float*)d_in[5];
    const float* out_w = (const float*)d_in[6];
    const float* out_b = (const float*)d_in[7];
    const float* ln1_s = (const float*)d_in[8];
    const float* ln1_b = (const float*)d_in[9];
    const float* w1 = (const float*)d_in[10];
    const float* b1 = (const float*)d_in[11];
    const float* w2 = (const float*)d_in[12];
    const float* b2 = (const float*)d_in[13];
    const float* ln2_s = (const float*)d_in[14];
    const float* ln2_b = (const float*)d_in[15];
    const float* fus_w1 = (const float*)d_in[16];
    const float* fus_b1 = (const float*)d_in[17];
    const float* fus_w2 = (const float*)d_in[18];
    const float* fus_b2 = (const float*)d_in[19];
    const float* cls_w = (const float*)d_in[20];
    const float* cls_b = (const float*)d_in[21];
    float* out = (float*)d_out;

    float *px, *py, *pqkv, *ppp, *pcp, *pu, *pc0;
    cudaGetSymbolAddress((void**)&px, g_x);
    cudaGetSymbolAddress((void**)&py, g_y);
    cudaGetSymbolAddress((void**)&pqkv, g_qkv);
    cudaGetSymbolAddress((void**)&ppp, g_pproj);
    cudaGetSymbolAddress((void**)&pcp, g_cproj);
    cudaGetSymbolAddress((void**)&pu, g_u);
    cudaGetSymbolAddress((void**)&pc0, g_c0);

    __nv_bfloat16 *pxh, *pxl, *pch, *pcl, *phh, *phl, *pph, *ppl;
    __nv_bfloat16 *pqwh, *pqwl, *powh, *powl, *pw1h, *pw1l, *pw2h, *pw2l, *pfwh, *pfwl;
    cudaGetSymbolAddress((void**)&pxh, g_xh);
    cudaGetSymbolAddress((void**)&pxl, g_xl);
    cudaGetSymbolAddress((void**)&pch, g_ctxh);
    cudaGetSymbolAddress((void**)&pcl, g_ctxl);
    cudaGetSymbolAddress((void**)&phh, g_hh);
    cudaGetSymbolAddress((void**)&phl, g_hl2);
    cudaGetSymbolAddress((void**)&pph, g_ph);
    cudaGetSymbolAddress((void**)&ppl, g_pl);
    cudaGetSymbolAddress((void**)&pqwh, g_qkvwh);
    cudaGetSymbolAddress((void**)&pqwl, g_qkvwl);
    cudaGetSymbolAddress((void**)&powh, g_outwh);
    cudaGetSymbolAddress((void**)&powl, g_outwl);
    cudaGetSymbolAddress((void**)&pw1h, g_w1h);
    cudaGetSymbolAddress((void**)&pw1l, g_w1l);
    cudaGetSymbolAddress((void**)&pw2h, g_w2h);
    cudaGetSymbolAddress((void**)&pw2l, g_w2l);
    cudaGetSymbolAddress((void**)&pfwh, g_fw1h);
    cudaGetSymbolAddress((void**)&pfwl, g_fw1l);

    cudaFuncSetAttribute(final_kernel, cudaFuncAttributeMaxDynamicSharedMemorySize, SMEM_FINAL);
    cudaFuncSetAttribute(gemm_bf16<true, false, false, true, false, false>, cudaFuncAttributeMaxDynamicSharedMemorySize, GEMM_SMEM);
    cudaFuncSetAttribute(gemm_bf16<true, true, false, true, false, false>, cudaFuncAttributeMaxDynamicSharedMemorySize, GEMM_SMEM);
    cudaFuncSetAttribute(gemm_bf16<true, false, true, false, true, false>, cudaFuncAttributeMaxDynamicSharedMemorySize, GEMM_SMEM);
    cudaFuncSetAttribute(gemm_bf16<false, false, false, true, false, false>, cudaFuncAttributeMaxDynamicSharedMemorySize, GEMM_SMEM);
    cudaFuncSetAttribute(gemm_bf16<true, false, false, true, false, true>, cudaFuncAttributeMaxDynamicSharedMemorySize, GEMM_SMEM);

    // streams/events for graph-captured fork (host objects, created once)
    static cudaStream_t s1 = nullptr, s2 = nullptr;
    static cudaEvent_t ev0 = nullptr, ev1 = nullptr, ev2 = nullptr;
    if (!s1) {
        cudaStreamCreateWithFlags(&s1, cudaStreamNonBlocking);
        cudaStreamCreateWithFlags(&s2, cudaStreamNonBlocking);
        cudaEventCreateWithFlags(&ev0, cudaEventDisableTiming);
        cudaEventCreateWithFlags(&ev1, cudaEventDisableTiming);
        cudaEventCreateWithFlags(&ev2, cudaEventDisableTiming);
    }

    // fork
    cudaEventRecord(ev0, 0);
    cudaStreamWaitEvent(s1, ev0, 0);
    cudaStreamWaitEvent(s2, ev0, 0);

    // branch s1: fusion prep + pproj
    prep_fus_kernel<<<1024, 256, 0, s1>>>(fus_w1, patches);
    gemm_bf16<false, false, false, true, false, false><<<dim3(D / BN, B * P / BM), 256, GEMM_SMEM, s1>>>(
        pph, ppl, DINO, pfwh, pfwl, DINO + D, nullptr, nullptr, ppp, nullptr, nullptr, D, DINO);
    cudaEventRecord(ev1, s1);

    // branch s2: u + c0
    u_kernel<<<M_ENC / 8, 256, 0, s2>>>(tokens, cls_w, cls_b, fus_w2, fus_b2, pu, pc0);
    cudaEventRecord(ev2, s2);

    // main branch: encoder
    prep_enc_kernel<<<1024, 256>>>(qkv_w, out_w, w1, w2, tokens, tok_emb, pos_emb);

    for (int l = 0; l < L; l++) {
        gemm_bf16<true, false, false, true, false, false><<<dim3(3 * D / BN, M_ENC / BM), 256, GEMM_SMEM>>>(
            pxh, pxl, D, pqwh + (size_t)l * 3 * D * D, pqwl + (size_t)l * 3 * D * D, D,
            qkv_b + (size_t)l * 3 * D, nullptr, pqkv, nullptr, nullptr, 3 * D, D);
        attn_kernel<<<B * H, 256>>>(pqkv, pch, pcl);
        gemm_bf16<true, true, false, true, false, false><<<dim3(D / BN, M_ENC / BM), 256, GEMM_SMEM>>>(
            pch, pcl, D, powh + (size_t)l * D * D, powl + (size_t)l * D * D, D,
            out_b + (size_t)l * D, px, py, nullptr, nullptr, D, D);
        ln_kernel<<<M_ENC, 256>>>(py, ln1_s + (size_t)l * D, ln1_b + (size_t)l * D, px, pxh, pxl);
        gemm_bf16<true, false, true, false, true, false><<<dim3(DFF / BN, M_ENC / BM), 256, GEMM_SMEM>>>(
            pxh, pxl, D, pw1h + (size_t)l * DFF * D, pw1l + (size_t)l * DFF * D, D,
            b1 + (size_t)l * DFF, nullptr, nullptr, phh, phl, DFF, D);
        gemm_bf16<true, true, false, true, false, false><<<dim3(D / BN, M_ENC / BM), 256, GEMM_SMEM>>>(
            phh, phl, DFF, pw2h + (size_t)l * D * DFF, pw2l + (size_t)l * D * DFF, DFF,
            b2 + (size_t)l * D, px, py, nullptr, nullptr, D, DFF);
        ln_kernel<<<M_ENC, 256>>>(py, ln2_s + (size_t)l * D, ln2_b + (size_t)l * D, px, pxh, pxl);
    }

    // join: cproj needs fus_w1 split (s1 branch)
    cudaStreamWaitEvent(0, ev1, 0);
    gemm_bf16<true, false, false, true, false, true><<<dim3(D / BN, M_ENC / BM), 256, GEMM_SMEM>>>(
        pxh, pxl, D, pfwh + DINO, pfwl + DINO, DINO + D,
        fus_b1, nullptr, pcp, nullptr, nullptr, D, D);

    cudaStreamWaitEvent(0, ev2, 0);
    final_kernel<<<dim3(B, P / PT, T / TT), 512, SMEM_FINAL>>>(ppp, pcp, pu, pc0, out);
}